// round 1
// baseline (speedup 1.0000x reference)
#include <cuda_runtime.h>

#define DIM 256
#define RPB 16   // rows per block in the main kernel

// g_U[c*256 + a] = (Re, Im) of U[a][c]  (amplitude a of evolved basis column c),
// interleaved so one 8-byte load feeds one packed f32x2 FMA.
__device__ float2 g_U[DIM * DIM];

union F2U {
    unsigned long long u;
    float2 f;
};

// ---------------------------------------------------------------------------
// Kernel 1: build U from q_weights. 256 blocks (one per basis column),
// 256 threads (one per amplitude). Evolves the column in shared memory.
// Wire w acts on bit (7-w)  (PennyLane MSB-first convention).
// ---------------------------------------------------------------------------
__global__ void build_u_kernel(const float* __restrict__ qw) {
    __shared__ float sr[DIM];
    __shared__ float si[DIM];
    const int t = threadIdx.x;
    const int col = blockIdx.x;

    sr[t] = (t == col) ? 1.0f : 0.0f;
    si[t] = 0.0f;
    __syncthreads();

    for (int l = 0; l < 2; ++l) {
        // 8 wires: RY then RZ per wire (fused into one pair update)
        for (int w = 0; w < 8; ++w) {
            const int bit = 1 << (7 - w);
            const float ty = qw[(l * 8 + w) * 2 + 0];
            const float tz = qw[(l * 8 + w) * 2 + 1];
            float sy, cy, sz, cz;
            sincosf(0.5f * ty, &sy, &cy);
            sincosf(0.5f * tz, &sz, &cz);

            const float ar = sr[t], ai = si[t];
            const float pr = sr[t ^ bit], pi = si[t ^ bit];

            // RY: new0 = c*a0 - s*a1 ; new1 = s*a0 + c*a1
            float nr, ni;
            if (t & bit) { nr = cy * ar + sy * pr; ni = cy * ai + sy * pi; }
            else         { nr = cy * ar - sy * pr; ni = cy * ai - sy * pi; }

            // RZ: |0> component *= e^{-i tz/2}, |1> component *= e^{+i tz/2}
            float rr, ri;
            if (t & bit) { rr = cz * nr - sz * ni; ri = cz * ni + sz * nr; }
            else         { rr = cz * nr + sz * ni; ri = cz * ni - sz * nr; }

            __syncthreads();
            sr[t] = rr; si[t] = ri;
            __syncthreads();
        }
        // CNOT chain: control i (bit 7-i), target i+1 (bit 6-i)
        for (int i = 0; i < 7; ++i) {
            const int cb = 1 << (7 - i);
            const int tb = 1 << (6 - i);
            const int src = (t & cb) ? (t ^ tb) : t;
            const float nr = sr[src], ni = si[src];
            __syncthreads();
            sr[t] = nr; si[t] = ni;
            __syncthreads();
        }
    }
    g_U[col * DIM + t] = make_float2(sr[t], si[t]);
}

// ---------------------------------------------------------------------------
// Kernel 2: per-row  y = U x  (packed f32x2 complex accumulation),
// then 16 expectation values, batchnorm, 16->8->2 MLP.
// 256 threads handle RPB rows; thread a owns amplitude a for all rows.
// ---------------------------------------------------------------------------
__global__ void __launch_bounds__(256)
qml_kernel(const float* __restrict__ x, int B,
           const float* __restrict__ gg, const float* __restrict__ bb,
           const float* __restrict__ rm, const float* __restrict__ rv,
           const float* __restrict__ W1, const float* __restrict__ b1,
           const float* __restrict__ W2, const float* __restrict__ b2,
           float* __restrict__ out) {
    // buf holds (x,x) duplicated pairs during the GEMM, then is overwritten
    // with (y_re, y_im) for the expectation phase. 16*256*8 = 32 KB.
    __shared__ unsigned long long buf[RPB][DIM];
    __shared__ float wsum[8][RPB];
    __shared__ float norms[RPB];

    const int t = threadIdx.x;
    const int lane = t & 31;
    const int warp = t >> 5;
    const int row0 = blockIdx.x * RPB;

    // ---- load x (duplicated as f32x2) + per-row squared norms ----
    float nn[RPB];
#pragma unroll
    for (int r = 0; r < RPB; ++r) {
        const int row = row0 + r;
        const float v = (row < B) ? x[(size_t)row * DIM + t] : 0.0f;
        nn[r] = v * v;
        F2U p; p.f = make_float2(v, v);
        buf[r][t] = p.u;
    }
#pragma unroll
    for (int off = 16; off; off >>= 1) {
#pragma unroll
        for (int r = 0; r < RPB; ++r)
            nn[r] += __shfl_xor_sync(0xffffffffu, nn[r], off);
    }
    if (lane == 0) {
#pragma unroll
        for (int r = 0; r < RPB; ++r) wsum[warp][r] = nn[r];
    }
    __syncthreads();
    if (t < RPB) {
        float s = 0.0f;
#pragma unroll
        for (int w = 0; w < 8; ++w) s += wsum[w][t];
        norms[t] = s;
    }

    // ---- GEMM phase: y[a] = sum_c U[a][c] * x[c], packed re/im ----
    unsigned long long acc[RPB];
#pragma unroll
    for (int r = 0; r < RPB; ++r) acc[r] = 0ull;  // bit pattern of (0.f, 0.f)

    const unsigned long long* Up =
        reinterpret_cast<const unsigned long long*>(g_U) + t;
#pragma unroll 4
    for (int c = 0; c < DIM; ++c) {
        const unsigned long long u = Up[(size_t)c * DIM];
#pragma unroll
        for (int r = 0; r < RPB; ++r) {
            asm("fma.rn.f32x2 %0, %1, %2, %0;"
                : "+l"(acc[r])
                : "l"(u), "l"(buf[r][c]));
        }
    }
    __syncthreads();   // everyone done reading x
#pragma unroll
    for (int r = 0; r < RPB; ++r) buf[r][t] = acc[r];
    __syncthreads();   // y visible to all

    // ---- expectation phase: warp w handles rows 2w and 2w+1 ----
    for (int rr = 0; rr < 2; ++rr) {
        const int r = warp * 2 + rr;
        const int row = row0 + r;

        float z[8], xp[8];
#pragma unroll
        for (int i = 0; i < 8; ++i) { z[i] = 0.0f; xp[i] = 0.0f; }

#pragma unroll
        for (int k = 0; k < 8; ++k) {
            const int a = lane + 32 * k;
            F2U y; y.u = buf[r][a];
            const float p = y.f.x * y.f.x + y.f.y * y.f.y;
#pragma unroll
            for (int i = 0; i < 8; ++i) {
                const int bit = 1 << (7 - i);
                z[i] += (a & bit) ? -p : p;
                // sum over ALL a of Re(conj(y_a) * y_{a^bit}) == 2 * pair-sum,
                // which is exactly the PauliX expectation numerator.
                F2U yp; yp.u = buf[r][a ^ bit];
                xp[i] += y.f.x * yp.f.x + y.f.y * yp.f.y;
            }
        }
#pragma unroll
        for (int off = 16; off; off >>= 1) {
#pragma unroll
            for (int i = 0; i < 8; ++i) {
                z[i]  += __shfl_xor_sync(0xffffffffu, z[i],  off);
                xp[i] += __shfl_xor_sync(0xffffffffu, xp[i], off);
            }
        }

        if (lane == 0 && row < B) {
            const float inv_n = 1.0f / norms[r];
            float q[16];
#pragma unroll
            for (int i = 0; i < 8; ++i) {
                q[i]     = z[i] * inv_n;
                q[8 + i] = xp[i] * inv_n;
            }
            // batchnorm (eval mode)
            float h[16];
#pragma unroll
            for (int i = 0; i < 16; ++i)
                h[i] = gg[i] * (q[i] - rm[i]) * rsqrtf(rv[i] + 1e-5f) + bb[i];
            // Linear(16,8) + ReLU
            float hh[8];
#pragma unroll
            for (int j = 0; j < 8; ++j) {
                float s = b1[j];
#pragma unroll
                for (int i = 0; i < 16; ++i) s += h[i] * W1[i * 8 + j];
                hh[j] = fmaxf(s, 0.0f);
            }
            // Linear(8,2)
#pragma unroll
            for (int k2 = 0; k2 < 2; ++k2) {
                float s = b2[k2];
#pragma unroll
                for (int j = 0; j < 8; ++j) s += hh[j] * W2[j * 2 + k2];
                out[(size_t)row * 2 + k2] = s;
            }
        }
    }
}

// ---------------------------------------------------------------------------
extern "C" void kernel_launch(void* const* d_in, const int* in_sizes, int n_in,
                              void* d_out, int out_size) {
    const float* x  = (const float*)d_in[0];
    const float* qw = (const float*)d_in[1];
    const float* gg = (const float*)d_in[2];
    const float* bb = (const float*)d_in[3];
    const float* rm = (const float*)d_in[4];
    const float* rv = (const float*)d_in[5];
    const float* W1 = (const float*)d_in[6];
    const float* b1 = (const float*)d_in[7];
    const float* W2 = (const float*)d_in[8];
    const float* b2 = (const float*)d_in[9];
    float* out = (float*)d_out;

    const int B = in_sizes[0] / DIM;
    if (B <= 0) return;

    build_u_kernel<<<DIM, DIM>>>(qw);
    const int grid = (B + RPB - 1) / RPB;
    qml_kernel<<<grid, 256>>>(x, B, gg, bb, rm, rv, W1, b1, W2, b2, out);
}

// round 5
// speedup vs baseline: 1.0053x; 1.0053x over previous
#include <cuda_runtime.h>
#include <cuda_bf16.h>
#include <cstdint>

#define DIM 256

// ---------------------------------------------------------------------------
// Global state
//   g_U[c*256 + a] = U[a][c]  (fp32 complex)
//   g_Bfrag: B operands in exact mma.m16n8k16 per-lane fragment layout.
//     flat index = ((comp*2 + hl)*16 + ks)*1024 + nt*32 + lane   (uint2 each)
//     comp: 0=re 1=im ; hl: 0=hi 1=lo ; ks: k-step (16 k per step) ; nt: n-tile (8 n)
// ---------------------------------------------------------------------------
__device__ float2 g_U[DIM * DIM];
__device__ uint2 g_Bfrag[2 * 2 * 16 * 32 * 32];

// ---------------------------------------------------------------------------
// Kernel 1: build U (verified in round 1)
// ---------------------------------------------------------------------------
__global__ void build_u_kernel(const float* __restrict__ qw) {
    __shared__ float sr[DIM];
    __shared__ float si[DIM];
    const int t = threadIdx.x;
    const int col = blockIdx.x;
    sr[t] = (t == col) ? 1.0f : 0.0f;
    si[t] = 0.0f;
    __syncthreads();
    for (int l = 0; l < 2; ++l) {
        for (int w = 0; w < 8; ++w) {
            const int bit = 1 << (7 - w);
            const float ty = qw[(l * 8 + w) * 2 + 0];
            const float tz = qw[(l * 8 + w) * 2 + 1];
            float sy, cy, sz, cz;
            sincosf(0.5f * ty, &sy, &cy);
            sincosf(0.5f * tz, &sz, &cz);
            const float ar = sr[t], ai = si[t];
            const float pr = sr[t ^ bit], pi = si[t ^ bit];
            float nr, ni;
            if (t & bit) { nr = cy * ar + sy * pr; ni = cy * ai + sy * pi; }
            else         { nr = cy * ar - sy * pr; ni = cy * ai - sy * pi; }
            float rr, ri;
            if (t & bit) { rr = cz * nr - sz * ni; ri = cz * ni + sz * nr; }
            else         { rr = cz * nr + sz * ni; ri = cz * ni - sz * nr; }
            __syncthreads();
            sr[t] = rr; si[t] = ri;
            __syncthreads();
        }
        for (int i = 0; i < 7; ++i) {
            const int cb = 1 << (7 - i);
            const int tb = 1 << (6 - i);
            const int src = (t & cb) ? (t ^ tb) : t;
            const float nr = sr[src], ni = si[src];
            __syncthreads();
            sr[t] = nr; si[t] = ni;
            __syncthreads();
        }
    }
    g_U[col * DIM + t] = make_float2(sr[t], si[t]);
}

// ---------------------------------------------------------------------------
// Kernel 2: build B fragments (hi/lo bf16 of W[k][n]; W = [U_re ; U_im] cols)
// ---------------------------------------------------------------------------
__global__ void u_to_bfrag_kernel() {
    const int tid = blockIdx.x * 256 + threadIdx.x;
    const int lane = tid & 31;
    const int nt = (tid >> 5) & 31;
    const int ks = (tid >> 10) & 15;
    const int hl = (tid >> 14) & 1;
    const int comp = (tid >> 15) & 1;
    const int g = lane >> 2, t = lane & 3;
    const int n = nt * 8 + g;
    const int k0 = ks * 16 + t * 2;
    const int kk[4] = {k0, k0 + 1, k0 + 8, k0 + 9};
    unsigned short h[4];
#pragma unroll
    for (int j = 0; j < 4; ++j) {
        const float2 u = g_U[kk[j] * DIM + n];
        float w = comp ? u.y : u.x;
        if (hl) {
            const __nv_bfloat16 wh = __float2bfloat16(w);
            w = w - __bfloat162float(wh);
        }
        const __nv_bfloat16 wb = __float2bfloat16(w);
        h[j] = *reinterpret_cast<const unsigned short*>(&wb);
    }
    uint2 val;
    val.x = (uint32_t)h[0] | ((uint32_t)h[1] << 16);
    val.y = (uint32_t)h[2] | ((uint32_t)h[3] << 16);
    g_Bfrag[tid] = val;
}

// ---------------------------------------------------------------------------
// mma.sync helpers
// ---------------------------------------------------------------------------
__device__ __forceinline__ void mma16816(float* c,
                                         uint32_t a0, uint32_t a1, uint32_t a2, uint32_t a3,
                                         uint32_t b0, uint32_t b1) {
    asm volatile(
        "mma.sync.aligned.m16n8k16.row.col.f32.bf16.bf16.f32 "
        "{%0,%1,%2,%3}, {%4,%5,%6,%7}, {%8,%9}, {%0,%1,%2,%3};"
        : "+f"(c[0]), "+f"(c[1]), "+f"(c[2]), "+f"(c[3])
        : "r"(a0), "r"(a1), "r"(a2), "r"(a3), "r"(b0), "r"(b1));
}

__device__ __forceinline__ void cvt_hilo(float2 v, uint32_t& hi, uint32_t& lo) {
    __nv_bfloat162 h = __float22bfloat162_rn(v);
    hi = *reinterpret_cast<const uint32_t*>(&h);
    float2 r = make_float2(v.x - __bfloat162float(h.x), v.y - __bfloat162float(h.y));
    __nv_bfloat162 l = __float22bfloat162_rn(r);
    lo = *reinterpret_cast<const uint32_t*>(&l);
}

// ---------------------------------------------------------------------------
// Kernel 3: main GEMM + expectations + BN + MLP.
// CTA = 128 rows. Warp grid 2(m)x4(n); warp tile 64x64.
// Two component passes (re, im); expectations separable across components.
// ---------------------------------------------------------------------------
extern __shared__ float ybuf[];   // [32][258] f32 = 33 KB

__global__ void __launch_bounds__(256, 1)
qml_mma_kernel(const float* __restrict__ x, int Btot,
               const float* __restrict__ gg, const float* __restrict__ bb,
               const float* __restrict__ rm, const float* __restrict__ rv,
               const float* __restrict__ W1, const float* __restrict__ b1,
               const float* __restrict__ W2, const float* __restrict__ b2,
               float* __restrict__ out) {
    __shared__ float s_part[128][16];
    __shared__ float s_norm[128];

    const int tid = threadIdx.x;
    const int lane = tid & 31;
    const int warp = tid >> 5;
    const int wm = warp >> 2;          // 0..1  (m position)
    const int wn = warp & 3;           // 0..3  (n position)
    const int g = lane >> 2;           // 0..7
    const int t = lane & 3;            // 0..3
    const int ctaRow = blockIdx.x * 128;
    const int rowW = ctaRow + wm * 64; // warp's first row

#pragma unroll 1
    for (int comp = 0; comp < 2; ++comp) {
        float acc[4][8][4];
#pragma unroll
        for (int mt = 0; mt < 4; ++mt)
#pragma unroll
            for (int nt = 0; nt < 8; ++nt)
#pragma unroll
                for (int j = 0; j < 4; ++j) acc[mt][nt][j] = 0.0f;

        float nacc[4][2];
#pragma unroll
        for (int mt = 0; mt < 4; ++mt) { nacc[mt][0] = 0.0f; nacc[mt][1] = 0.0f; }

        const uint2* __restrict__ Bh = g_Bfrag + comp * 32768 + (wn * 8) * 32 + lane;
        const uint2* __restrict__ Bl = Bh + 16384;

#pragma unroll 2
        for (int ks = 0; ks < 16; ++ks) {
            uint2 bh[8], bl[8];
#pragma unroll
            for (int nt = 0; nt < 8; ++nt) {
                bh[nt] = Bh[ks * 1024 + nt * 32];
                bl[nt] = Bl[ks * 1024 + nt * 32];
            }
            const int kcol = ks * 16 + t * 2;
#pragma unroll
            for (int mt = 0; mt < 4; ++mt) {
                const int r0 = rowW + mt * 16 + g;
                const int r1 = r0 + 8;
                const float2* p0 = reinterpret_cast<const float2*>(x + (size_t)r0 * DIM + kcol);
                const float2* p1 = reinterpret_cast<const float2*>(x + (size_t)r1 * DIM + kcol);
                const float2 z2 = make_float2(0.0f, 0.0f);
                const float2 v00 = (r0 < Btot) ? p0[0] : z2;  // (m=g,   k=t2)
                const float2 v01 = (r0 < Btot) ? p0[4] : z2;  // (m=g,   k=t2+8)
                const float2 v10 = (r1 < Btot) ? p1[0] : z2;  // (m=g+8, k=t2)
                const float2 v11 = (r1 < Btot) ? p1[4] : z2;  // (m=g+8, k=t2+8)

                if (comp == 0 && wn == 0) {
                    nacc[mt][0] += v00.x * v00.x + v00.y * v00.y + v01.x * v01.x + v01.y * v01.y;
                    nacc[mt][1] += v10.x * v10.x + v10.y * v10.y + v11.x * v11.x + v11.y * v11.y;
                }

                uint32_t a0h, a0l, a1h, a1l, a2h, a2l, a3h, a3l;
                cvt_hilo(v00, a0h, a0l);
                cvt_hilo(v10, a1h, a1l);
                cvt_hilo(v01, a2h, a2l);
                cvt_hilo(v11, a3h, a3l);

#pragma unroll
                for (int nt = 0; nt < 8; ++nt) {
                    mma16816(acc[mt][nt], a0h, a1h, a2h, a3h, bh[nt].x, bh[nt].y);
                    mma16816(acc[mt][nt], a0h, a1h, a2h, a3h, bl[nt].x, bl[nt].y);
                    mma16816(acc[mt][nt], a0l, a1l, a2l, a3l, bh[nt].x, bh[nt].y);
                }
            }
        }

        // norms (once, from the re pass, warp_n == 0 only)
        if (comp == 0 && wn == 0) {
#pragma unroll
            for (int mt = 0; mt < 4; ++mt)
#pragma unroll
                for (int h = 0; h < 2; ++h) {
                    float v = nacc[mt][h];
                    v += __shfl_xor_sync(0xffffffffu, v, 1);
                    v += __shfl_xor_sync(0xffffffffu, v, 2);
                    if (t == 0) s_norm[wm * 64 + mt * 16 + g + 8 * h] = v;
                }
        }

        // ---- epilogue: 4 sub-steps of 32 rows through smem ----
#pragma unroll 1
        for (int sub = 0; sub < 4; ++sub) {
            __syncthreads();   // prev consumers done / norms visible / ybuf WAR
            if (wm == (sub >> 1)) {
                const int mt0 = (sub & 1) * 2;
#pragma unroll
                for (int mtl = 0; mtl < 2; ++mtl) {
                    const int mt = mt0 + mtl;
#pragma unroll
                    for (int nt = 0; nt < 8; ++nt) {
                        const int c = wn * 64 + nt * 8 + t * 2;
                        const int rA = mtl * 16 + g;
                        *reinterpret_cast<float2*>(&ybuf[rA * 258 + c]) =
                            make_float2(acc[mt][nt][0], acc[mt][nt][1]);
                        *reinterpret_cast<float2*>(&ybuf[(rA + 8) * 258 + c]) =
                            make_float2(acc[mt][nt][2], acc[mt][nt][3]);
                    }
                }
            }
            __syncthreads();

            // quadratics: warp handles 4 rows
#pragma unroll
            for (int rr = 0; rr < 4; ++rr) {
                const int r = warp * 4 + rr;        // local 0..31
                float yv[8];
#pragma unroll
                for (int k = 0; k < 8; ++k) yv[k] = ybuf[r * 258 + lane + 32 * k];

                float z[8], xp[8];
#pragma unroll
                for (int i = 0; i < 8; ++i) { z[i] = 0.0f; xp[i] = 0.0f; }
#pragma unroll
                for (int k = 0; k < 8; ++k) {
                    const float p = yv[k] * yv[k];
                    const int a = lane + 32 * k;
#pragma unroll
                    for (int i = 0; i < 8; ++i) {
                        const int bit = 1 << (7 - i);
                        z[i] += (a & bit) ? -p : p;
                    }
                    xp[2] += yv[k] * yv[k ^ 1];   // bit 32
                    xp[1] += yv[k] * yv[k ^ 2];   // bit 64
                    xp[0] += yv[k] * yv[k ^ 4];   // bit 128
                }
#pragma unroll
                for (int i = 3; i < 8; ++i) {
                    const int b = 1 << (7 - i);
                    float a2 = 0.0f;
#pragma unroll
                    for (int k = 0; k < 8; ++k)
                        a2 += yv[k] * __shfl_xor_sync(0xffffffffu, yv[k], b);
                    xp[i] = a2;
                }
#pragma unroll
                for (int off = 16; off; off >>= 1) {
#pragma unroll
                    for (int i = 0; i < 8; ++i) {
                        z[i]  += __shfl_xor_sync(0xffffffffu, z[i],  off);
                        xp[i] += __shfl_xor_sync(0xffffffffu, xp[i], off);
                    }
                }

                if (lane == 0) {
                    const int sr = sub * 32 + r;
                    if (comp == 0) {
#pragma unroll
                        for (int i = 0; i < 8; ++i) {
                            s_part[sr][i] = z[i];
                            s_part[sr][8 + i] = xp[i];
                        }
                    } else {
                        const int grow = ctaRow + sr;
                        if (grow < Btot) {
                            const float inv_n = 1.0f / s_norm[sr];
                            float q[16];
#pragma unroll
                            for (int i = 0; i < 8; ++i) {
                                q[i]     = (s_part[sr][i] + z[i]) * inv_n;
                                q[8 + i] = (s_part[sr][8 + i] + xp[i]) * inv_n;
                            }
                            float h[16];
#pragma unroll
                            for (int i = 0; i < 16; ++i)
                                h[i] = gg[i] * (q[i] - rm[i]) * rsqrtf(rv[i] + 1e-5f) + bb[i];
                            float hh[8];
#pragma unroll
                            for (int j = 0; j < 8; ++j) {
                                float s = b1[j];
#pragma unroll
                                for (int i = 0; i < 16; ++i) s += h[i] * W1[i * 8 + j];
                                hh[j] = fmaxf(s, 0.0f);
                            }
#pragma unroll
                            for (int k2 = 0; k2 < 2; ++k2) {
                                float s = b2[k2];
#pragma unroll
                                for (int j = 0; j < 8; ++j) s += hh[j] * W2[j * 2 + k2];
                                out[(size_t)grow * 2 + k2] = s;
                            }
                        }
                    }
                }
            }
        }
        __syncthreads();   // done with ybuf before next comp overwrites
    }
}

// ---------------------------------------------------------------------------
extern "C" void kernel_launch(void* const* d_in, const int* in_sizes, int n_in,
                              void* d_out, int out_size) {
    const float* x  = (const float*)d_in[0];
    const float* qw = (const float*)d_in[1];
    const float* gg = (const float*)d_in[2];
    const float* bb = (const float*)d_in[3];
    const float* rm = (const float*)d_in[4];
    const float* rv = (const float*)d_in[5];
    const float* W1 = (const float*)d_in[6];
    const float* b1 = (const float*)d_in[7];
    const float* W2 = (const float*)d_in[8];
    const float* b2 = (const float*)d_in[9];
    float* out = (float*)d_out;

    const int Btot = in_sizes[0] / DIM;
    if (Btot <= 0) return;

    build_u_kernel<<<DIM, DIM>>>(qw);
    u_to_bfrag_kernel<<<DIM, 256>>>();
    const int grid = (Btot + 127) / 128;
    qml_mma_kernel<<<grid, 256, 32 * 258 * 4>>>(x, Btot, gg, bb, rm, rv,
                                                W1, b1, W2, b2, out);
}

// round 6
// speedup vs baseline: 1.7998x; 1.7903x over previous
#include <cuda_runtime.h>
#include <cuda_bf16.h>
#include <cstdint>

#define DIM 256

// ---------------------------------------------------------------------------
// Global state
//   g_U[c*256 + a] = U[a][c]  (fp32 complex)
//   g_Bfrag: B operands in exact mma.m16n8k16 per-lane fragment layout.
//     flat index = ((comp*2 + hl)*16 + ks)*1024 + nt*32 + lane   (uint2 each)
//     comp: 0=re 1=im ; hl: 0=hi 1=lo ; ks: k-step (16 k) ; nt: n-tile (8 n)
// ---------------------------------------------------------------------------
__device__ float2 g_U[DIM * DIM];
__device__ uint2 g_Bfrag[2 * 2 * 16 * 32 * 32];

// ---------------------------------------------------------------------------
// Kernel 1: build U (verified)
// ---------------------------------------------------------------------------
__global__ void build_u_kernel(const float* __restrict__ qw) {
    __shared__ float sr[DIM];
    __shared__ float si[DIM];
    const int t = threadIdx.x;
    const int col = blockIdx.x;
    sr[t] = (t == col) ? 1.0f : 0.0f;
    si[t] = 0.0f;
    __syncthreads();
    for (int l = 0; l < 2; ++l) {
        for (int w = 0; w < 8; ++w) {
            const int bit = 1 << (7 - w);
            const float ty = qw[(l * 8 + w) * 2 + 0];
            const float tz = qw[(l * 8 + w) * 2 + 1];
            float sy, cy, sz, cz;
            sincosf(0.5f * ty, &sy, &cy);
            sincosf(0.5f * tz, &sz, &cz);
            const float ar = sr[t], ai = si[t];
            const float pr = sr[t ^ bit], pi = si[t ^ bit];
            float nr, ni;
            if (t & bit) { nr = cy * ar + sy * pr; ni = cy * ai + sy * pi; }
            else         { nr = cy * ar - sy * pr; ni = cy * ai - sy * pi; }
            float rr, ri;
            if (t & bit) { rr = cz * nr - sz * ni; ri = cz * ni + sz * nr; }
            else         { rr = cz * nr + sz * ni; ri = cz * ni - sz * nr; }
            __syncthreads();
            sr[t] = rr; si[t] = ri;
            __syncthreads();
        }
        for (int i = 0; i < 7; ++i) {
            const int cb = 1 << (7 - i);
            const int tb = 1 << (6 - i);
            const int src = (t & cb) ? (t ^ tb) : t;
            const float nr = sr[src], ni = si[src];
            __syncthreads();
            sr[t] = nr; si[t] = ni;
            __syncthreads();
        }
    }
    g_U[col * DIM + t] = make_float2(sr[t], si[t]);
}

// ---------------------------------------------------------------------------
// Kernel 2: build B fragments (hi/lo bf16 of W[k][n]; W = [U_re ; U_im] cols)
// ---------------------------------------------------------------------------
__global__ void u_to_bfrag_kernel() {
    const int tid = blockIdx.x * 256 + threadIdx.x;
    const int lane = tid & 31;
    const int nt = (tid >> 5) & 31;
    const int ks = (tid >> 10) & 15;
    const int hl = (tid >> 14) & 1;
    const int comp = (tid >> 15) & 1;
    const int g = lane >> 2, t = lane & 3;
    const int n = nt * 8 + g;
    const int k0 = ks * 16 + t * 2;
    const int kk[4] = {k0, k0 + 1, k0 + 8, k0 + 9};
    unsigned short h[4];
#pragma unroll
    for (int j = 0; j < 4; ++j) {
        const float2 u = g_U[kk[j] * DIM + n];
        float w = comp ? u.y : u.x;
        if (hl) {
            const __nv_bfloat16 wh = __float2bfloat16(w);
            w = w - __bfloat162float(wh);
        }
        const __nv_bfloat16 wb = __float2bfloat16(w);
        h[j] = *reinterpret_cast<const unsigned short*>(&wb);
    }
    uint2 val;
    val.x = (uint32_t)h[0] | ((uint32_t)h[1] << 16);
    val.y = (uint32_t)h[2] | ((uint32_t)h[3] << 16);
    g_Bfrag[tid] = val;
}

// ---------------------------------------------------------------------------
// mma.sync helpers
// ---------------------------------------------------------------------------
__device__ __forceinline__ void mma16816(float* c,
                                         uint32_t a0, uint32_t a1, uint32_t a2, uint32_t a3,
                                         uint32_t b0, uint32_t b1) {
    asm volatile(
        "mma.sync.aligned.m16n8k16.row.col.f32.bf16.bf16.f32 "
        "{%0,%1,%2,%3}, {%4,%5,%6,%7}, {%8,%9}, {%0,%1,%2,%3};"
        : "+f"(c[0]), "+f"(c[1]), "+f"(c[2]), "+f"(c[3])
        : "r"(a0), "r"(a1), "r"(a2), "r"(a3), "r"(b0), "r"(b1));
}

__device__ __forceinline__ void cvt_hilo(float2 v, uint32_t& hi, uint32_t& lo) {
    __nv_bfloat162 h = __float22bfloat162_rn(v);
    hi = *reinterpret_cast<const uint32_t*>(&h);
    float2 r = make_float2(v.x - __bfloat162float(h.x), v.y - __bfloat162float(h.y));
    __nv_bfloat162 l = __float22bfloat162_rn(r);
    lo = *reinterpret_cast<const uint32_t*>(&l);
}

// ---------------------------------------------------------------------------
// Kernel 3: main GEMM + expectations + BN + MLP.
// CTA = 64 rows, 8 warps in 2(m) x 4(n); warp tile 32 x 64.
// acc[2][8][4] = 64 regs/thread -> no spills (the R5 failure mode).
// ---------------------------------------------------------------------------
extern __shared__ float ybuf[];   // [32][258] f32 = 33 KB

__global__ void __launch_bounds__(256, 1)
qml_mma_kernel(const float* __restrict__ x, int Btot,
               const float* __restrict__ gg, const float* __restrict__ bb,
               const float* __restrict__ rm, const float* __restrict__ rv,
               const float* __restrict__ W1, const float* __restrict__ b1,
               const float* __restrict__ W2, const float* __restrict__ b2,
               float* __restrict__ out) {
    __shared__ float s_part[64][16];
    __shared__ float s_norm[64];

    const int tid = threadIdx.x;
    const int lane = tid & 31;
    const int warp = tid >> 5;
    const int wm = warp >> 2;          // 0..1  (m position, 32 rows each)
    const int wn = warp & 3;           // 0..3  (n position, 64 cols each)
    const int g = lane >> 2;           // 0..7
    const int t = lane & 3;            // 0..3
    const int ctaRow = blockIdx.x * 64;
    const int rowW = ctaRow + wm * 32; // warp's first row

#pragma unroll 1
    for (int comp = 0; comp < 2; ++comp) {
        float acc[2][8][4];
#pragma unroll
        for (int mt = 0; mt < 2; ++mt)
#pragma unroll
            for (int nt = 0; nt < 8; ++nt)
#pragma unroll
                for (int j = 0; j < 4; ++j) acc[mt][nt][j] = 0.0f;

        float nacc[2][2];
        nacc[0][0] = nacc[0][1] = nacc[1][0] = nacc[1][1] = 0.0f;

        const uint2* __restrict__ Bh = g_Bfrag + comp * 32768 + (wn * 8) * 32 + lane;
        const uint2* __restrict__ Bl = Bh + 16384;

#pragma unroll 2
        for (int ks = 0; ks < 16; ++ks) {
            const int kcol = ks * 16 + t * 2;
#pragma unroll
            for (int mt = 0; mt < 2; ++mt) {
                const int r0 = rowW + mt * 16 + g;
                const int r1 = r0 + 8;
                const float2* p0 = reinterpret_cast<const float2*>(x + (size_t)r0 * DIM + kcol);
                const float2* p1 = reinterpret_cast<const float2*>(x + (size_t)r1 * DIM + kcol);
                const float2 z2 = make_float2(0.0f, 0.0f);
                const float2 v00 = (r0 < Btot) ? p0[0] : z2;  // (m=g,   k=2t)
                const float2 v01 = (r0 < Btot) ? p0[4] : z2;  // (m=g,   k=2t+8)
                const float2 v10 = (r1 < Btot) ? p1[0] : z2;  // (m=g+8, k=2t)
                const float2 v11 = (r1 < Btot) ? p1[4] : z2;  // (m=g+8, k=2t+8)

                if (comp == 0 && wn == 0) {
                    nacc[mt][0] += v00.x * v00.x + v00.y * v00.y + v01.x * v01.x + v01.y * v01.y;
                    nacc[mt][1] += v10.x * v10.x + v10.y * v10.y + v11.x * v11.x + v11.y * v11.y;
                }

                uint32_t a0h, a0l, a1h, a1l, a2h, a2l, a3h, a3l;
                cvt_hilo(v00, a0h, a0l);
                cvt_hilo(v10, a1h, a1l);
                cvt_hilo(v01, a2h, a2l);
                cvt_hilo(v11, a3h, a3l);

#pragma unroll
                for (int nt = 0; nt < 8; ++nt) {
                    const uint2 bh = Bh[ks * 1024 + nt * 32];
                    const uint2 bl = Bl[ks * 1024 + nt * 32];
                    mma16816(acc[mt][nt], a0h, a1h, a2h, a3h, bh.x, bh.y);
                    mma16816(acc[mt][nt], a0h, a1h, a2h, a3h, bl.x, bl.y);
                    mma16816(acc[mt][nt], a0l, a1l, a2l, a3l, bh.x, bh.y);
                }
            }
        }

        // norms (once, from the re pass, wn == 0 warps)
        if (comp == 0 && wn == 0) {
#pragma unroll
            for (int mt = 0; mt < 2; ++mt)
#pragma unroll
                for (int h = 0; h < 2; ++h) {
                    float v = nacc[mt][h];
                    v += __shfl_xor_sync(0xffffffffu, v, 1);
                    v += __shfl_xor_sync(0xffffffffu, v, 2);
                    if (t == 0) s_norm[wm * 32 + mt * 16 + g + 8 * h] = v;
                }
        }

        // ---- epilogue: 2 sub-steps of 32 rows through smem ----
#pragma unroll 1
        for (int sub = 0; sub < 2; ++sub) {
            __syncthreads();   // prev consumers done / norms visible / ybuf WAR
            if (wm == sub) {
#pragma unroll
                for (int mt = 0; mt < 2; ++mt) {
#pragma unroll
                    for (int nt = 0; nt < 8; ++nt) {
                        const int c = wn * 64 + nt * 8 + t * 2;
                        const int rA = mt * 16 + g;
                        *reinterpret_cast<float2*>(&ybuf[rA * 258 + c]) =
                            make_float2(acc[mt][nt][0], acc[mt][nt][1]);
                        *reinterpret_cast<float2*>(&ybuf[(rA + 8) * 258 + c]) =
                            make_float2(acc[mt][nt][2], acc[mt][nt][3]);
                    }
                }
            }
            __syncthreads();

            // quadratics: each warp handles 4 of the 32 rows
#pragma unroll
            for (int rr = 0; rr < 4; ++rr) {
                const int r = warp * 4 + rr;        // local 0..31
                float yv[8];
#pragma unroll
                for (int k = 0; k < 8; ++k) yv[k] = ybuf[r * 258 + lane + 32 * k];

                float z[8], xp[8];
#pragma unroll
                for (int i = 0; i < 8; ++i) { z[i] = 0.0f; xp[i] = 0.0f; }
#pragma unroll
                for (int k = 0; k < 8; ++k) {
                    const float p = yv[k] * yv[k];
                    const int a = lane + 32 * k;
#pragma unroll
                    for (int i = 0; i < 8; ++i) {
                        const int bit = 1 << (7 - i);
                        z[i] += (a & bit) ? -p : p;
                    }
                    xp[2] += yv[k] * yv[k ^ 1];   // bit 32
                    xp[1] += yv[k] * yv[k ^ 2];   // bit 64
                    xp[0] += yv[k] * yv[k ^ 4];   // bit 128
                }
#pragma unroll
                for (int i = 3; i < 8; ++i) {
                    const int b = 1 << (7 - i);
                    float a2 = 0.0f;
#pragma unroll
                    for (int k = 0; k < 8; ++k)
                        a2 += yv[k] * __shfl_xor_sync(0xffffffffu, yv[k], b);
                    xp[i] = a2;
                }
#pragma unroll
                for (int off = 16; off; off >>= 1) {
#pragma unroll
                    for (int i = 0; i < 8; ++i) {
                        z[i]  += __shfl_xor_sync(0xffffffffu, z[i],  off);
                        xp[i] += __shfl_xor_sync(0xffffffffu, xp[i], off);
                    }
                }

                if (lane == 0) {
                    const int sr = sub * 32 + r;
                    if (comp == 0) {
#pragma unroll
                        for (int i = 0; i < 8; ++i) {
                            s_part[sr][i] = z[i];
                            s_part[sr][8 + i] = xp[i];
                        }
                    } else {
                        const int grow = ctaRow + sr;
                        if (grow < Btot) {
                            const float inv_n = 1.0f / s_norm[sr];
                            float q[16];
#pragma unroll
                            for (int i = 0; i < 8; ++i) {
                                q[i]     = (s_part[sr][i] + z[i]) * inv_n;
                                q[8 + i] = (s_part[sr][8 + i] + xp[i]) * inv_n;
                            }
                            float h[16];
#pragma unroll
                            for (int i = 0; i < 16; ++i)
                                h[i] = gg[i] * (q[i] - rm[i]) * rsqrtf(rv[i] + 1e-5f) + bb[i];
                            float hh[8];
#pragma unroll
                            for (int j = 0; j < 8; ++j) {
                                float s = b1[j];
#pragma unroll
                                for (int i = 0; i < 16; ++i) s += h[i] * W1[i * 8 + j];
                                hh[j] = fmaxf(s, 0.0f);
                            }
#pragma unroll
                            for (int k2 = 0; k2 < 2; ++k2) {
                                float s = b2[k2];
#pragma unroll
                                for (int j = 0; j < 8; ++j) s += hh[j] * W2[j * 2 + k2];
                                out[(size_t)grow * 2 + k2] = s;
                            }
                        }
                    }
                }
            }
        }
        __syncthreads();   // done with ybuf before next comp overwrites
    }
}

// ---------------------------------------------------------------------------
extern "C" void kernel_launch(void* const* d_in, const int* in_sizes, int n_in,
                              void* d_out, int out_size) {
    const float* x  = (const float*)d_in[0];
    const float* qw = (const float*)d_in[1];
    const float* gg = (const float*)d_in[2];
    const float* bb = (const float*)d_in[3];
    const float* rm = (const float*)d_in[4];
    const float* rv = (const float*)d_in[5];
    const float* W1 = (const float*)d_in[6];
    const float* b1 = (const float*)d_in[7];
    const float* W2 = (const float*)d_in[8];
    const float* b2 = (const float*)d_in[9];
    float* out = (float*)d_out;

    const int Btot = in_sizes[0] / DIM;
    if (Btot <= 0) return;

    build_u_kernel<<<DIM, DIM>>>(qw);
    u_to_bfrag_kernel<<<DIM, 256>>>();
    const int grid = (Btot + 63) / 64;
    qml_mma_kernel<<<grid, 256, 32 * 258 * 4>>>(x, Btot, gg, bb, rm, rv,
                                                W1, b1, W2, b2, out);
}

// round 8
// speedup vs baseline: 1.9140x; 1.0634x over previous
#include <cuda_runtime.h>
#include <cuda_bf16.h>
#include <cstdint>

#define DIM 256

// ---------------------------------------------------------------------------
// Global state
//   g_U[c*256 + a] = U[a][c]  (fp32 complex)
//   g_BfragI: interleaved hi/lo B operands in mma.m16n8k16 per-lane layout.
//     uint4 {hi.b0, hi.b1, lo.b0, lo.b1} at flat index
//       ((comp*16 + ks)*32 + nt)*32 + lane
//     comp: 0=re 1=im ; ks: k-step (16 k) ; nt: global n-tile (8 n each)
// ---------------------------------------------------------------------------
__device__ float2 g_U[DIM * DIM];
__device__ uint4 g_BfragI[2 * 16 * 32 * 32];

// ---------------------------------------------------------------------------
// Kernel 1: build U (verified)
// ---------------------------------------------------------------------------
__global__ void build_u_kernel(const float* __restrict__ qw) {
    __shared__ float sr[DIM];
    __shared__ float si[DIM];
    const int t = threadIdx.x;
    const int col = blockIdx.x;
    sr[t] = (t == col) ? 1.0f : 0.0f;
    si[t] = 0.0f;
    __syncthreads();
    for (int l = 0; l < 2; ++l) {
        for (int w = 0; w < 8; ++w) {
            const int bit = 1 << (7 - w);
            const float ty = qw[(l * 8 + w) * 2 + 0];
            const float tz = qw[(l * 8 + w) * 2 + 1];
            float sy, cy, sz, cz;
            sincosf(0.5f * ty, &sy, &cy);
            sincosf(0.5f * tz, &sz, &cz);
            const float ar = sr[t], ai = si[t];
            const float pr = sr[t ^ bit], pi = si[t ^ bit];
            float nr, ni;
            if (t & bit) { nr = cy * ar + sy * pr; ni = cy * ai + sy * pi; }
            else         { nr = cy * ar - sy * pr; ni = cy * ai - sy * pi; }
            float rr, ri;
            if (t & bit) { rr = cz * nr - sz * ni; ri = cz * ni + sz * nr; }
            else         { rr = cz * nr + sz * ni; ri = cz * ni - sz * nr; }
            __syncthreads();
            sr[t] = rr; si[t] = ri;
            __syncthreads();
        }
        for (int i = 0; i < 7; ++i) {
            const int cb = 1 << (7 - i);
            const int tb = 1 << (6 - i);
            const int src = (t & cb) ? (t ^ tb) : t;
            const float nr = sr[src], ni = si[src];
            __syncthreads();
            sr[t] = nr; si[t] = ni;
            __syncthreads();
        }
    }
    g_U[col * DIM + t] = make_float2(sr[t], si[t]);
}

// ---------------------------------------------------------------------------
// Kernel 2: build interleaved B fragments.
// 32768 threads; tid = comp<<14 | ks<<10 | nt<<5 | lane == flat uint4 slot.
// B frag (m16n8k16): b0 = W[k0..k0+1][n], b1 = W[k0+8..k0+9][n],
//   k0 = ks*16 + t*2, n = nt*8 + g.  W[k][n] = U[n][k] (comp component).
// ---------------------------------------------------------------------------
__global__ void u_to_bfrag_kernel() {
    const int tid = blockIdx.x * 256 + threadIdx.x;
    const int lane = tid & 31;
    const int nt = (tid >> 5) & 31;
    const int ks = (tid >> 10) & 15;
    const int comp = (tid >> 14) & 1;
    const int g = lane >> 2, t = lane & 3;
    const int n = nt * 8 + g;
    const int k0 = ks * 16 + t * 2;
    const int kk[4] = {k0, k0 + 1, k0 + 8, k0 + 9};
    unsigned short hh[4], ll[4];
#pragma unroll
    for (int j = 0; j < 4; ++j) {
        const float2 u = g_U[kk[j] * DIM + n];
        const float w = comp ? u.y : u.x;
        const __nv_bfloat16 wh = __float2bfloat16(w);
        const float rsd = w - __bfloat162float(wh);
        const __nv_bfloat16 wl = __float2bfloat16(rsd);
        hh[j] = *reinterpret_cast<const unsigned short*>(&wh);
        ll[j] = *reinterpret_cast<const unsigned short*>(&wl);
    }
    uint4 val;
    val.x = (uint32_t)hh[0] | ((uint32_t)hh[1] << 16);
    val.y = (uint32_t)hh[2] | ((uint32_t)hh[3] << 16);
    val.z = (uint32_t)ll[0] | ((uint32_t)ll[1] << 16);
    val.w = (uint32_t)ll[2] | ((uint32_t)ll[3] << 16);
    g_BfragI[tid] = val;
}

// ---------------------------------------------------------------------------
// mma.sync helpers
// ---------------------------------------------------------------------------
__device__ __forceinline__ void mma16816(float* c,
                                         uint32_t a0, uint32_t a1, uint32_t a2, uint32_t a3,
                                         uint32_t b0, uint32_t b1) {
    asm volatile(
        "mma.sync.aligned.m16n8k16.row.col.f32.bf16.bf16.f32 "
        "{%0,%1,%2,%3}, {%4,%5,%6,%7}, {%8,%9}, {%0,%1,%2,%3};"
        : "+f"(c[0]), "+f"(c[1]), "+f"(c[2]), "+f"(c[3])
        : "r"(a0), "r"(a1), "r"(a2), "r"(a3), "r"(b0), "r"(b1));
}

__device__ __forceinline__ void cvt_hilo(float2 v, uint32_t& hi, uint32_t& lo) {
    __nv_bfloat162 h = __float22bfloat162_rn(v);
    hi = *reinterpret_cast<const uint32_t*>(&h);
    float2 r = make_float2(v.x - __bfloat162float(h.x), v.y - __bfloat162float(h.y));
    __nv_bfloat162 l = __float22bfloat162_rn(r);
    lo = *reinterpret_cast<const uint32_t*>(&l);
}

// ---------------------------------------------------------------------------
// Kernel 3: main GEMM + expectations + BN + MLP.
// CTA = 64 rows, 8 warps in 2(m) x 4(n); warp tile 32 x 64.
// B fragments loaded ONCE per ks (8 x LDG.128, hoisted) and reused across mt.
// ---------------------------------------------------------------------------
extern __shared__ float ybuf[];   // [32][258] f32 = 33 KB

__global__ void __launch_bounds__(256, 1)
qml_mma_kernel(const float* __restrict__ x, int Btot,
               const float* __restrict__ gg, const float* __restrict__ bb,
               const float* __restrict__ rm, const float* __restrict__ rv,
               const float* __restrict__ W1, const float* __restrict__ b1,
               const float* __restrict__ W2, const float* __restrict__ b2,
               float* __restrict__ out) {
    __shared__ float s_part[64][16];
    __shared__ float s_norm[64];

    const int tid = threadIdx.x;
    const int lane = tid & 31;
    const int warp = tid >> 5;
    const int wm = warp >> 2;          // 0..1  (m position, 32 rows each)
    const int wn = warp & 3;           // 0..3  (n position, 64 cols each)
    const int g = lane >> 2;           // 0..7
    const int t = lane & 3;            // 0..3
    const int ctaRow = blockIdx.x * 64;
    const int rowW = ctaRow + wm * 32; // warp's first row

#pragma unroll 1
    for (int comp = 0; comp < 2; ++comp) {
        float acc[2][8][4];
#pragma unroll
        for (int mt = 0; mt < 2; ++mt)
#pragma unroll
            for (int nt = 0; nt < 8; ++nt)
#pragma unroll
                for (int j = 0; j < 4; ++j) acc[mt][nt][j] = 0.0f;

        float nacc[2][2];
        nacc[0][0] = nacc[0][1] = nacc[1][0] = nacc[1][1] = 0.0f;

        const uint4* __restrict__ Bp = g_BfragI + comp * 16384 + (wn * 8) * 32 + lane;

#pragma unroll 2
        for (int ks = 0; ks < 16; ++ks) {
            // ---- 8 independent LDG.128: both hi and lo for all nt ----
            uint4 b[8];
#pragma unroll
            for (int nt = 0; nt < 8; ++nt) b[nt] = Bp[ks * 1024 + nt * 32];

            const int kcol = ks * 16 + t * 2;
#pragma unroll
            for (int mt = 0; mt < 2; ++mt) {
                const int r0 = rowW + mt * 16 + g;
                const int r1 = r0 + 8;
                const float2* p0 = reinterpret_cast<const float2*>(x + (size_t)r0 * DIM + kcol);
                const float2* p1 = reinterpret_cast<const float2*>(x + (size_t)r1 * DIM + kcol);
                const float2 z2 = make_float2(0.0f, 0.0f);
                const float2 v00 = (r0 < Btot) ? p0[0] : z2;  // (m=g,   k=2t)
                const float2 v01 = (r0 < Btot) ? p0[4] : z2;  // (m=g,   k=2t+8)
                const float2 v10 = (r1 < Btot) ? p1[0] : z2;  // (m=g+8, k=2t)
                const float2 v11 = (r1 < Btot) ? p1[4] : z2;  // (m=g+8, k=2t+8)

                if (comp == 0 && wn == 0) {
                    nacc[mt][0] += v00.x * v00.x + v00.y * v00.y + v01.x * v01.x + v01.y * v01.y;
                    nacc[mt][1] += v10.x * v10.x + v10.y * v10.y + v11.x * v11.x + v11.y * v11.y;
                }

                uint32_t a0h, a0l, a1h, a1l, a2h, a2l, a3h, a3l;
                cvt_hilo(v00, a0h, a0l);
                cvt_hilo(v10, a1h, a1l);
                cvt_hilo(v01, a2h, a2l);
                cvt_hilo(v11, a3h, a3l);

#pragma unroll
                for (int nt = 0; nt < 8; ++nt) {
                    mma16816(acc[mt][nt], a0h, a1h, a2h, a3h, b[nt].x, b[nt].y);
                    mma16816(acc[mt][nt], a0h, a1h, a2h, a3h, b[nt].z, b[nt].w);
                    mma16816(acc[mt][nt], a0l, a1l, a2l, a3l, b[nt].x, b[nt].y);
                }
            }
        }

        // norms (once, from the re pass, wn == 0 warps)
        if (comp == 0 && wn == 0) {
#pragma unroll
            for (int mt = 0; mt < 2; ++mt)
#pragma unroll
                for (int h = 0; h < 2; ++h) {
                    float v = nacc[mt][h];
                    v += __shfl_xor_sync(0xffffffffu, v, 1);
                    v += __shfl_xor_sync(0xffffffffu, v, 2);
                    if (t == 0) s_norm[wm * 32 + mt * 16 + g + 8 * h] = v;
                }
        }

        // ---- epilogue: 2 sub-steps of 32 rows through smem ----
#pragma unroll 1
        for (int sub = 0; sub < 2; ++sub) {
            __syncthreads();   // prev consumers done / norms visible / ybuf WAR
            if (wm == sub) {
#pragma unroll
                for (int mt = 0; mt < 2; ++mt) {
#pragma unroll
                    for (int nt = 0; nt < 8; ++nt) {
                        const int c = wn * 64 + nt * 8 + t * 2;
                        const int rA = mt * 16 + g;
                        *reinterpret_cast<float2*>(&ybuf[rA * 258 + c]) =
                            make_float2(acc[mt][nt][0], acc[mt][nt][1]);
                        *reinterpret_cast<float2*>(&ybuf[(rA + 8) * 258 + c]) =
                            make_float2(acc[mt][nt][2], acc[mt][nt][3]);
                    }
                }
            }
            __syncthreads();

            // quadratics: each warp handles 4 of the 32 rows
#pragma unroll
            for (int rr = 0; rr < 4; ++rr) {
                const int r = warp * 4 + rr;        // local 0..31
                float yv[8];
#pragma unroll
                for (int k = 0; k < 8; ++k) yv[k] = ybuf[r * 258 + lane + 32 * k];

                float z[8], xp[8];
#pragma unroll
                for (int i = 0; i < 8; ++i) { z[i] = 0.0f; xp[i] = 0.0f; }
#pragma unroll
                for (int k = 0; k < 8; ++k) {
                    const float p = yv[k] * yv[k];
                    const int a = lane + 32 * k;
#pragma unroll
                    for (int i = 0; i < 8; ++i) {
                        const int bit = 1 << (7 - i);
                        z[i] += (a & bit) ? -p : p;
                    }
                    xp[2] += yv[k] * yv[k ^ 1];   // bit 32
                    xp[1] += yv[k] * yv[k ^ 2];   // bit 64
                    xp[0] += yv[k] * yv[k ^ 4];   // bit 128
                }
#pragma unroll
                for (int i = 3; i < 8; ++i) {
                    const int b = 1 << (7 - i);
                    float a2 = 0.0f;
#pragma unroll
                    for (int k = 0; k < 8; ++k)
                        a2 += yv[k] * __shfl_xor_sync(0xffffffffu, yv[k], b);
                    xp[i] = a2;
                }
#pragma unroll
                for (int off = 16; off; off >>= 1) {
#pragma unroll
                    for (int i = 0; i < 8; ++i) {
                        z[i]  += __shfl_xor_sync(0xffffffffu, z[i],  off);
                        xp[i] += __shfl_xor_sync(0xffffffffu, xp[i], off);
                    }
                }

                if (lane == 0) {
                    const int sr = sub * 32 + r;
                    if (comp == 0) {
#pragma unroll
                        for (int i = 0; i < 8; ++i) {
                            s_part[sr][i] = z[i];
                            s_part[sr][8 + i] = xp[i];
                        }
                    } else {
                        const int grow = ctaRow + sr;
                        if (grow < Btot) {
                            const float inv_n = 1.0f / s_norm[sr];
                            float q[16];
#pragma unroll
                            for (int i = 0; i < 8; ++i) {
                                q[i]     = (s_part[sr][i] + z[i]) * inv_n;
                                q[8 + i] = (s_part[sr][8 + i] + xp[i]) * inv_n;
                            }
                            float h[16];
#pragma unroll
                            for (int i = 0; i < 16; ++i)
                                h[i] = gg[i] * (q[i] - rm[i]) * rsqrtf(rv[i] + 1e-5f) + bb[i];
                            float hh[8];
#pragma unroll
                            for (int j = 0; j < 8; ++j) {
                                float s = b1[j];
#pragma unroll
                                for (int i = 0; i < 16; ++i) s += h[i] * W1[i * 8 + j];
                                hh[j] = fmaxf(s, 0.0f);
                            }
#pragma unroll
                            for (int k2 = 0; k2 < 2; ++k2) {
                                float s = b2[k2];
#pragma unroll
                                for (int j = 0; j < 8; ++j) s += hh[j] * W2[j * 2 + k2];
                                out[(size_t)grow * 2 + k2] = s;
                            }
                        }
                    }
                }
            }
        }
        __syncthreads();   // done with ybuf before next comp overwrites
    }
}

// ---------------------------------------------------------------------------
extern "C" void kernel_launch(void* const* d_in, const int* in_sizes, int n_in,
                              void* d_out, int out_size) {
    const float* x  = (const float*)d_in[0];
    const float* qw = (const float*)d_in[1];
    const float* gg = (const float*)d_in[2];
    const float* bb = (const float*)d_in[3];
    const float* rm = (const float*)d_in[4];
    const float* rv = (const float*)d_in[5];
    const float* W1 = (const float*)d_in[6];
    const float* b1 = (const float*)d_in[7];
    const float* W2 = (const float*)d_in[8];
    const float* b2 = (const float*)d_in[9];
    float* out = (float*)d_out;

    const int Btot = in_sizes[0] / DIM;
    if (Btot <= 0) return;

    build_u_kernel<<<DIM, DIM>>>(qw);
    u_to_bfrag_kernel<<<128, 256>>>();
    const int grid = (Btot + 63) / 64;
    qml_mma_kernel<<<grid, 256, 32 * 258 * 4>>>(x, Btot, gg, bb, rm, rv,
                                                W1, b1, W2, b2, out);
}

// round 9
// speedup vs baseline: 2.0060x; 1.0481x over previous
#include <cuda_runtime.h>
#include <cuda_bf16.h>
#include <cstdint>

#define DIM 256

// ---------------------------------------------------------------------------
// Global state
//   g_U[c*256 + a] = U[a][c]  (fp32 complex)
//   g_BfragI: interleaved hi/lo B operands in mma.m16n8k16 per-lane layout.
//     uint4 {hi.b0, hi.b1, lo.b0, lo.b1} at flat index
//       ((comp*16 + ks)*32 + nt)*32 + lane
// ---------------------------------------------------------------------------
__device__ float2 g_U[DIM * DIM];
__device__ uint4 g_BfragI[2 * 16 * 32 * 32];

// ---------------------------------------------------------------------------
// Kernel 1: build U (verified)
// ---------------------------------------------------------------------------
__global__ void build_u_kernel(const float* __restrict__ qw) {
    __shared__ float sr[DIM];
    __shared__ float si[DIM];
    const int t = threadIdx.x;
    const int col = blockIdx.x;
    sr[t] = (t == col) ? 1.0f : 0.0f;
    si[t] = 0.0f;
    __syncthreads();
    for (int l = 0; l < 2; ++l) {
        for (int w = 0; w < 8; ++w) {
            const int bit = 1 << (7 - w);
            const float ty = qw[(l * 8 + w) * 2 + 0];
            const float tz = qw[(l * 8 + w) * 2 + 1];
            float sy, cy, sz, cz;
            sincosf(0.5f * ty, &sy, &cy);
            sincosf(0.5f * tz, &sz, &cz);
            const float ar = sr[t], ai = si[t];
            const float pr = sr[t ^ bit], pi = si[t ^ bit];
            float nr, ni;
            if (t & bit) { nr = cy * ar + sy * pr; ni = cy * ai + sy * pi; }
            else         { nr = cy * ar - sy * pr; ni = cy * ai - sy * pi; }
            float rr, ri;
            if (t & bit) { rr = cz * nr - sz * ni; ri = cz * ni + sz * nr; }
            else         { rr = cz * nr + sz * ni; ri = cz * ni - sz * nr; }
            __syncthreads();
            sr[t] = rr; si[t] = ri;
            __syncthreads();
        }
        for (int i = 0; i < 7; ++i) {
            const int cb = 1 << (7 - i);
            const int tb = 1 << (6 - i);
            const int src = (t & cb) ? (t ^ tb) : t;
            const float nr = sr[src], ni = si[src];
            __syncthreads();
            sr[t] = nr; si[t] = ni;
            __syncthreads();
        }
    }
    g_U[col * DIM + t] = make_float2(sr[t], si[t]);
}

// ---------------------------------------------------------------------------
// Kernel 2: build interleaved B fragments (verified layout).
// ---------------------------------------------------------------------------
__global__ void u_to_bfrag_kernel() {
    const int tid = blockIdx.x * 256 + threadIdx.x;
    const int lane = tid & 31;
    const int nt = (tid >> 5) & 31;
    const int ks = (tid >> 10) & 15;
    const int comp = (tid >> 14) & 1;
    const int g = lane >> 2, t = lane & 3;
    const int n = nt * 8 + g;
    const int k0 = ks * 16 + t * 2;
    const int kk[4] = {k0, k0 + 1, k0 + 8, k0 + 9};
    unsigned short hh[4], ll[4];
#pragma unroll
    for (int j = 0; j < 4; ++j) {
        const float2 u = g_U[kk[j] * DIM + n];
        const float w = comp ? u.y : u.x;
        const __nv_bfloat16 wh = __float2bfloat16(w);
        const float rsd = w - __bfloat162float(wh);
        const __nv_bfloat16 wl = __float2bfloat16(rsd);
        hh[j] = *reinterpret_cast<const unsigned short*>(&wh);
        ll[j] = *reinterpret_cast<const unsigned short*>(&wl);
    }
    uint4 val;
    val.x = (uint32_t)hh[0] | ((uint32_t)hh[1] << 16);
    val.y = (uint32_t)hh[2] | ((uint32_t)hh[3] << 16);
    val.z = (uint32_t)ll[0] | ((uint32_t)ll[1] << 16);
    val.w = (uint32_t)ll[2] | ((uint32_t)ll[3] << 16);
    g_BfragI[tid] = val;
}

// ---------------------------------------------------------------------------
// mma.sync helpers
// ---------------------------------------------------------------------------
__device__ __forceinline__ void mma16816(float* c,
                                         uint32_t a0, uint32_t a1, uint32_t a2, uint32_t a3,
                                         uint32_t b0, uint32_t b1) {
    asm volatile(
        "mma.sync.aligned.m16n8k16.row.col.f32.bf16.bf16.f32 "
        "{%0,%1,%2,%3}, {%4,%5,%6,%7}, {%8,%9}, {%0,%1,%2,%3};"
        : "+f"(c[0]), "+f"(c[1]), "+f"(c[2]), "+f"(c[3])
        : "r"(a0), "r"(a1), "r"(a2), "r"(a3), "r"(b0), "r"(b1));
}

__device__ __forceinline__ void cvt_hilo(float2 v, uint32_t& hi, uint32_t& lo) {
    __nv_bfloat162 h = __float22bfloat162_rn(v);
    hi = *reinterpret_cast<const uint32_t*>(&h);
    float2 r = make_float2(v.x - __bfloat162float(h.x), v.y - __bfloat162float(h.y));
    __nv_bfloat162 l = __float22bfloat162_rn(r);
    lo = *reinterpret_cast<const uint32_t*>(&l);
}

// ---------------------------------------------------------------------------
// Kernel 3: main GEMM + expectations + BN + MLP.
// CTA = 64 rows, 8 warps in 2(m) x 4(n); warp tile 32 x 64.
// occ-2 version: A fragments converted once per ks (registers), B streamed
// per-nt (1 transient uint4) -> ~110 regs, fits __launch_bounds__(256, 2).
// ---------------------------------------------------------------------------
extern __shared__ float ybuf[];   // [32][258] f32 = 33 KB

__global__ void __launch_bounds__(256, 2)
qml_mma_kernel(const float* __restrict__ x, int Btot,
               const float* __restrict__ gg, const float* __restrict__ bb,
               const float* __restrict__ rm, const float* __restrict__ rv,
               const float* __restrict__ W1, const float* __restrict__ b1,
               const float* __restrict__ W2, const float* __restrict__ b2,
               float* __restrict__ out) {
    __shared__ float s_part[64][16];
    __shared__ float s_norm[64];

    const int tid = threadIdx.x;
    const int lane = tid & 31;
    const int warp = tid >> 5;
    const int wm = warp >> 2;          // 0..1  (m position, 32 rows each)
    const int wn = warp & 3;           // 0..3  (n position, 64 cols each)
    const int g = lane >> 2;           // 0..7
    const int t = lane & 3;            // 0..3
    const int ctaRow = blockIdx.x * 64;
    const int rowW = ctaRow + wm * 32; // warp's first row

#pragma unroll 1
    for (int comp = 0; comp < 2; ++comp) {
        float acc[2][8][4];
#pragma unroll
        for (int mt = 0; mt < 2; ++mt)
#pragma unroll
            for (int nt = 0; nt < 8; ++nt)
#pragma unroll
                for (int j = 0; j < 4; ++j) acc[mt][nt][j] = 0.0f;

        float nacc[2][2];
        nacc[0][0] = nacc[0][1] = nacc[1][0] = nacc[1][1] = 0.0f;

        const uint4* __restrict__ Bp = g_BfragI + comp * 16384 + (wn * 8) * 32 + lane;

#pragma unroll 1
        for (int ks = 0; ks < 16; ++ks) {
            // ---- A fragments: load + cvt once per ks, reused across all nt ----
            uint32_t aH[2][4], aL[2][4];
            const int kcol = ks * 16 + t * 2;
#pragma unroll
            for (int mt = 0; mt < 2; ++mt) {
                const int r0 = rowW + mt * 16 + g;
                const int r1 = r0 + 8;
                const float2* p0 = reinterpret_cast<const float2*>(x + (size_t)r0 * DIM + kcol);
                const float2* p1 = reinterpret_cast<const float2*>(x + (size_t)r1 * DIM + kcol);
                const float2 z2 = make_float2(0.0f, 0.0f);
                const float2 v00 = (r0 < Btot) ? p0[0] : z2;  // (m=g,   k=2t)
                const float2 v01 = (r0 < Btot) ? p0[4] : z2;  // (m=g,   k=2t+8)
                const float2 v10 = (r1 < Btot) ? p1[0] : z2;  // (m=g+8, k=2t)
                const float2 v11 = (r1 < Btot) ? p1[4] : z2;  // (m=g+8, k=2t+8)

                if (comp == 0 && wn == 0) {
                    nacc[mt][0] += v00.x * v00.x + v00.y * v00.y + v01.x * v01.x + v01.y * v01.y;
                    nacc[mt][1] += v10.x * v10.x + v10.y * v10.y + v11.x * v11.x + v11.y * v11.y;
                }
                cvt_hilo(v00, aH[mt][0], aL[mt][0]);
                cvt_hilo(v10, aH[mt][1], aL[mt][1]);
                cvt_hilo(v01, aH[mt][2], aL[mt][2]);
                cvt_hilo(v11, aH[mt][3], aL[mt][3]);
            }

            // ---- B streamed per nt; 6 MMAs per load ----
#pragma unroll
            for (int nt = 0; nt < 8; ++nt) {
                const uint4 b = Bp[ks * 1024 + nt * 32];
#pragma unroll
                for (int mt = 0; mt < 2; ++mt) {
                    mma16816(acc[mt][nt], aH[mt][0], aH[mt][1], aH[mt][2], aH[mt][3], b.x, b.y);
                    mma16816(acc[mt][nt], aH[mt][0], aH[mt][1], aH[mt][2], aH[mt][3], b.z, b.w);
                    mma16816(acc[mt][nt], aL[mt][0], aL[mt][1], aL[mt][2], aL[mt][3], b.x, b.y);
                }
            }
        }

        // norms (once, from the re pass, wn == 0 warps)
        if (comp == 0 && wn == 0) {
#pragma unroll
            for (int mt = 0; mt < 2; ++mt)
#pragma unroll
                for (int h = 0; h < 2; ++h) {
                    float v = nacc[mt][h];
                    v += __shfl_xor_sync(0xffffffffu, v, 1);
                    v += __shfl_xor_sync(0xffffffffu, v, 2);
                    if (t == 0) s_norm[wm * 32 + mt * 16 + g + 8 * h] = v;
                }
        }

        // ---- epilogue: 2 sub-steps of 32 rows through smem ----
#pragma unroll 1
        for (int sub = 0; sub < 2; ++sub) {
            __syncthreads();   // prev consumers done / norms visible / ybuf WAR
            if (wm == sub) {
#pragma unroll
                for (int mt = 0; mt < 2; ++mt) {
#pragma unroll
                    for (int nt = 0; nt < 8; ++nt) {
                        const int c = wn * 64 + nt * 8 + t * 2;
                        const int rA = mt * 16 + g;
                        *reinterpret_cast<float2*>(&ybuf[rA * 258 + c]) =
                            make_float2(acc[mt][nt][0], acc[mt][nt][1]);
                        *reinterpret_cast<float2*>(&ybuf[(rA + 8) * 258 + c]) =
                            make_float2(acc[mt][nt][2], acc[mt][nt][3]);
                    }
                }
            }
            __syncthreads();

            // quadratics: each warp handles 4 of the 32 rows
#pragma unroll
            for (int rr = 0; rr < 4; ++rr) {
                const int r = warp * 4 + rr;        // local 0..31
                float yv[8];
#pragma unroll
                for (int k = 0; k < 8; ++k) yv[k] = ybuf[r * 258 + lane + 32 * k];

                float z[8], xp[8];
#pragma unroll
                for (int i = 0; i < 8; ++i) { z[i] = 0.0f; xp[i] = 0.0f; }
#pragma unroll
                for (int k = 0; k < 8; ++k) {
                    const float p = yv[k] * yv[k];
                    const int a = lane + 32 * k;
#pragma unroll
                    for (int i = 0; i < 8; ++i) {
                        const int bit = 1 << (7 - i);
                        z[i] += (a & bit) ? -p : p;
                    }
                    xp[2] += yv[k] * yv[k ^ 1];   // bit 32
                    xp[1] += yv[k] * yv[k ^ 2];   // bit 64
                    xp[0] += yv[k] * yv[k ^ 4];   // bit 128
                }
#pragma unroll
                for (int i = 3; i < 8; ++i) {
                    const int b = 1 << (7 - i);
                    float a2 = 0.0f;
#pragma unroll
                    for (int k = 0; k < 8; ++k)
                        a2 += yv[k] * __shfl_xor_sync(0xffffffffu, yv[k], b);
                    xp[i] = a2;
                }
#pragma unroll
                for (int off = 16; off; off >>= 1) {
#pragma unroll
                    for (int i = 0; i < 8; ++i) {
                        z[i]  += __shfl_xor_sync(0xffffffffu, z[i],  off);
                        xp[i] += __shfl_xor_sync(0xffffffffu, xp[i], off);
                    }
                }

                if (lane == 0) {
                    const int sr = sub * 32 + r;
                    if (comp == 0) {
#pragma unroll
                        for (int i = 0; i < 8; ++i) {
                            s_part[sr][i] = z[i];
                            s_part[sr][8 + i] = xp[i];
                        }
                    } else {
                        const int grow = ctaRow + sr;
                        if (grow < Btot) {
                            const float inv_n = 1.0f / s_norm[sr];
                            float q[16];
#pragma unroll
                            for (int i = 0; i < 8; ++i) {
                                q[i]     = (s_part[sr][i] + z[i]) * inv_n;
                                q[8 + i] = (s_part[sr][8 + i] + xp[i]) * inv_n;
                            }
                            float h[16];
#pragma unroll
                            for (int i = 0; i < 16; ++i)
                                h[i] = gg[i] * (q[i] - rm[i]) * rsqrtf(rv[i] + 1e-5f) + bb[i];
                            float hh[8];
#pragma unroll
                            for (int j = 0; j < 8; ++j) {
                                float s = b1[j];
#pragma unroll
                                for (int i = 0; i < 16; ++i) s += h[i] * W1[i * 8 + j];
                                hh[j] = fmaxf(s, 0.0f);
                            }
#pragma unroll
                            for (int k2 = 0; k2 < 2; ++k2) {
                                float s = b2[k2];
#pragma unroll
                                for (int j = 0; j < 8; ++j) s += hh[j] * W2[j * 2 + k2];
                                out[(size_t)grow * 2 + k2] = s;
                            }
                        }
                    }
                }
            }
        }
        __syncthreads();   // done with ybuf before next comp overwrites
    }
}

// ---------------------------------------------------------------------------
extern "C" void kernel_launch(void* const* d_in, const int* in_sizes, int n_in,
                              void* d_out, int out_size) {
    const float* x  = (const float*)d_in[0];
    const float* qw = (const float*)d_in[1];
    const float* gg = (const float*)d_in[2];
    const float* bb = (const float*)d_in[3];
    const float* rm = (const float*)d_in[4];
    const float* rv = (const float*)d_in[5];
    const float* W1 = (const float*)d_in[6];
    const float* b1 = (const float*)d_in[7];
    const float* W2 = (const float*)d_in[8];
    const float* b2 = (const float*)d_in[9];
    float* out = (float*)d_out;

    const int Btot = in_sizes[0] / DIM;
    if (Btot <= 0) return;

    build_u_kernel<<<DIM, DIM>>>(qw);
    u_to_bfrag_kernel<<<128, 256>>>();
    const int grid = (Btot + 63) / 64;
    qml_mma_kernel<<<grid, 256, 32 * 258 * 4>>>(x, Btot, gg, bb, rm, rv,
                                                W1, b1, W2, b2, out);
}

// round 10
// speedup vs baseline: 3.3124x; 1.6512x over previous
#include <cuda_runtime.h>
#include <cstdint>

#define DIM 256
#define FULL 0xffffffffu

// ---------------------------------------------------------------------------
// Single-kernel design: each warp evolves one row's 256-amplitude state
// through the circuit directly (butterflies + CNOT permutations), then
// computes the 16 expectations + BN + MLP. No U matrix, no GEMM.
//
// Amplitude layout: a = lane + 32*k  (lane = a[4:0], k = a[7:5]).
// Wire w acts on bit (7-w):
//   wires 0..2  -> register bits (k): in-register pair rotations
//   wires 3..7  -> lane bits: shfl_xor partner + per-thread signed constants
// CNOT(c=bit(7-i), t=bit(6-i)) chain i=0..6:
//   i=0,1  reg-reg  -> register swaps
//   i=2    reg-lane -> shfl_xor(16) on odd-k regs
//   i=3..6 lane-lane-> shfl.idx with src = (lane&c)? lane^t : lane
// Gate sign conventions transcribed from the round-1-verified build_u_kernel.
// ---------------------------------------------------------------------------
__global__ void __launch_bounds__(256)
qml_bfly_kernel(const float* __restrict__ x, int Btot,
                const float* __restrict__ qw,
                const float* __restrict__ gg, const float* __restrict__ bb,
                const float* __restrict__ rm, const float* __restrict__ rv,
                const float* __restrict__ W1, const float* __restrict__ b1,
                const float* __restrict__ W2, const float* __restrict__ b2,
                float* __restrict__ out) {
    __shared__ float s_gc[16][4];   // per gate: cy, sy, cz, sz

    const int tid = threadIdx.x;
    const int lane = tid & 31;
    const int warp = tid >> 5;

    if (tid < 16) {
        const float ty = qw[tid * 2 + 0];
        const float tz = qw[tid * 2 + 1];
        float sy, cy, sz, cz;
        sincosf(0.5f * ty, &sy, &cy);
        sincosf(0.5f * tz, &sz, &cz);
        s_gc[tid][0] = cy; s_gc[tid][1] = sy;
        s_gc[tid][2] = cz; s_gc[tid][3] = sz;
    }
    __syncthreads();

    const int stride = gridDim.x * 8;
    for (int row = blockIdx.x * 8 + warp; row < Btot; row += stride) {
        float ar[8], ai[8];
        const float* xr = x + (size_t)row * DIM + lane;
#pragma unroll
        for (int k = 0; k < 8; ++k) { ar[k] = xr[32 * k]; ai[k] = 0.0f; }

#pragma unroll
        for (int l = 0; l < 2; ++l) {
            // ---- 8 wires: RY then RZ ----
#pragma unroll
            for (int w = 0; w < 8; ++w) {
                const int gid = l * 8 + w;
                const float cy = s_gc[gid][0], sy = s_gc[gid][1];
                const float cz = s_gc[gid][2], sz = s_gc[gid][3];
                const int bit = 1 << (7 - w);
                if (bit >= 32) {
                    // register-bit wire: pairs (k0, k0|kb)
                    const int kb = bit >> 5;
#pragma unroll
                    for (int k0 = 0; k0 < 8; ++k0) {
                        if (!(k0 & kb)) {
                            const int k1 = k0 | kb;
                            const float n0r = cy * ar[k0] - sy * ar[k1];
                            const float n0i = cy * ai[k0] - sy * ai[k1];
                            const float n1r = sy * ar[k0] + cy * ar[k1];
                            const float n1i = sy * ai[k0] + cy * ai[k1];
                            // RZ: bit-clear -> e^{-i tz/2}, bit-set -> e^{+i tz/2}
                            ar[k0] = cz * n0r + sz * n0i;
                            ai[k0] = cz * n0i - sz * n0r;
                            ar[k1] = cz * n1r - sz * n1i;
                            ai[k1] = cz * n1i + sz * n1r;
                        }
                    }
                } else {
                    // lane-bit wire: partner via shfl_xor, per-thread signs
                    const float ssy = (lane & bit) ? sy : -sy;
                    const float ssz = (lane & bit) ? sz : -sz;
#pragma unroll
                    for (int k = 0; k < 8; ++k) {
                        const float pr = __shfl_xor_sync(FULL, ar[k], bit);
                        const float pi = __shfl_xor_sync(FULL, ai[k], bit);
                        const float nr = cy * ar[k] + ssy * pr;
                        const float ni = cy * ai[k] + ssy * pi;
                        ar[k] = cz * nr - ssz * ni;
                        ai[k] = cz * ni + ssz * nr;
                    }
                }
            }
            // ---- CNOT chain: control bit(7-i), target bit(6-i) ----
            {   // i=0: c=128 (k&4), t=64 (k^2): swap (4,6),(5,7)
                float t;
                t = ar[4]; ar[4] = ar[6]; ar[6] = t;
                t = ai[4]; ai[4] = ai[6]; ai[6] = t;
                t = ar[5]; ar[5] = ar[7]; ar[7] = t;
                t = ai[5]; ai[5] = ai[7]; ai[7] = t;
            }
            {   // i=1: c=64 (k&2), t=32 (k^1): swap (2,3),(6,7)
                float t;
                t = ar[2]; ar[2] = ar[3]; ar[3] = t;
                t = ai[2]; ai[2] = ai[3]; ai[3] = t;
                t = ar[6]; ar[6] = ar[7]; ar[7] = t;
                t = ai[6]; ai[6] = ai[7]; ai[7] = t;
            }
            // i=2: c=32 (k&1), t=16 (lane): odd k regs swap across lane bit 16
#pragma unroll
            for (int k = 1; k < 8; k += 2) {
                ar[k] = __shfl_xor_sync(FULL, ar[k], 16);
                ai[k] = __shfl_xor_sync(FULL, ai[k], 16);
            }
            // i=3..6: lane-lane: (16,8),(8,4),(4,2),(2,1)
#pragma unroll
            for (int cb = 16; cb >= 2; cb >>= 1) {
                const int src = (lane & cb) ? (lane ^ (cb >> 1)) : lane;
#pragma unroll
                for (int k = 0; k < 8; ++k) {
                    ar[k] = __shfl_sync(FULL, ar[k], src);
                    ai[k] = __shfl_sync(FULL, ai[k], src);
                }
            }
        }

        // ---- expectations ----
        float p[8], psum = 0.0f;
#pragma unroll
        for (int k = 0; k < 8; ++k) {
            p[k] = ar[k] * ar[k] + ai[k] * ai[k];
            psum += p[k];
        }
        float z[8], xp[8];
        // z for register bits (k-dependent signs)
        z[0] = (p[0] + p[1] + p[2] + p[3]) - (p[4] + p[5] + p[6] + p[7]); // bit128=k&4
        z[1] = (p[0] + p[1] + p[4] + p[5]) - (p[2] + p[3] + p[6] + p[7]); // bit64 =k&2
        z[2] = (p[0] + p[2] + p[4] + p[6]) - (p[1] + p[3] + p[5] + p[7]); // bit32 =k&1
        // z for lane bits: sign depends only on lane
#pragma unroll
        for (int i = 3; i < 8; ++i) {
            const int bit = 1 << (7 - i);
            z[i] = (lane & bit) ? -psum : psum;
        }
        // PauliX numerators: Sum_a Re(conj(y_a) y_{a^bit})
        xp[0] = xp[1] = xp[2] = 0.0f;
#pragma unroll
        for (int k = 0; k < 8; ++k) {
            xp[2] += ar[k] * ar[k ^ 1] + ai[k] * ai[k ^ 1];  // bit 32
            xp[1] += ar[k] * ar[k ^ 2] + ai[k] * ai[k ^ 2];  // bit 64
            xp[0] += ar[k] * ar[k ^ 4] + ai[k] * ai[k ^ 4];  // bit 128
        }
#pragma unroll
        for (int i = 3; i < 8; ++i) {
            const int bit = 1 << (7 - i);
            float acc = 0.0f;
#pragma unroll
            for (int k = 0; k < 8; ++k) {
                acc += ar[k] * __shfl_xor_sync(FULL, ar[k], bit);
                acc += ai[k] * __shfl_xor_sync(FULL, ai[k], bit);
            }
            xp[i] = acc;
        }
        // warp reduction of 17 values
#pragma unroll
        for (int off = 16; off; off >>= 1) {
            psum += __shfl_xor_sync(FULL, psum, off);
#pragma unroll
            for (int i = 0; i < 8; ++i) {
                z[i]  += __shfl_xor_sync(FULL, z[i],  off);
                xp[i] += __shfl_xor_sync(FULL, xp[i], off);
            }
        }

        if (lane == 0) {
            const float inv_n = 1.0f / psum;   // ||y||^2 == ||x||^2 (U unitary)
            float q[16];
#pragma unroll
            for (int i = 0; i < 8; ++i) {
                q[i]     = z[i] * inv_n;
                q[8 + i] = xp[i] * inv_n;
            }
            float h[16];
#pragma unroll
            for (int i = 0; i < 16; ++i)
                h[i] = gg[i] * (q[i] - rm[i]) * rsqrtf(rv[i] + 1e-5f) + bb[i];
            float hh[8];
#pragma unroll
            for (int j = 0; j < 8; ++j) {
                float s = b1[j];
#pragma unroll
                for (int i = 0; i < 16; ++i) s += h[i] * W1[i * 8 + j];
                hh[j] = fmaxf(s, 0.0f);
            }
#pragma unroll
            for (int k2 = 0; k2 < 2; ++k2) {
                float s = b2[k2];
#pragma unroll
                for (int j = 0; j < 8; ++j) s += hh[j] * W2[j * 2 + k2];
                out[(size_t)row * 2 + k2] = s;
            }
        }
    }
}

// ---------------------------------------------------------------------------
extern "C" void kernel_launch(void* const* d_in, const int* in_sizes, int n_in,
                              void* d_out, int out_size) {
    const float* x  = (const float*)d_in[0];
    const float* qw = (const float*)d_in[1];
    const float* gg = (const float*)d_in[2];
    const float* bb = (const float*)d_in[3];
    const float* rm = (const float*)d_in[4];
    const float* rv = (const float*)d_in[5];
    const float* W1 = (const float*)d_in[6];
    const float* b1 = (const float*)d_in[7];
    const float* W2 = (const float*)d_in[8];
    const float* b2 = (const float*)d_in[9];
    float* out = (float*)d_out;

    const int Btot = in_sizes[0] / DIM;
    if (Btot <= 0) return;

    qml_bfly_kernel<<<1024, 256>>>(x, Btot, qw, gg, bb, rm, rv,
                                   W1, b1, W2, b2, out);
}

// round 11
// speedup vs baseline: 4.1447x; 1.2513x over previous
#include <cuda_runtime.h>
#include <cstdint>

#define DIM 256
#define FULL 0xffffffffu

// merge(a,b,off): lanes with (lane&off)==0 end up holding a[l]+a[l^off],
// lanes with bit set hold b[l]+b[l^off]. One shfl per merged pair of values.
__device__ __forceinline__ float merge2(float a, float b, int off, int lane) {
    const bool sel = (lane & off) != 0;
    const float x = sel ? b : a;
    const float y = __shfl_xor_sync(FULL, sel ? a : b, off);
    return x + y;
}

// ---------------------------------------------------------------------------
// Warp-per-row direct circuit evolution.
// Amplitude layout: a = lane + 32*k (lane = a[4:0], k = a[7:5]).
// Layer 1 runs in REAL arithmetic (input is real, RY is real); its RZ phases
// are folded into a per-amplitude phase table composed with the layer-1 CNOT
// permutation. Layer 2 is fully complex (identical to the round-10-verified
// code). Reductions use WHT + tree-merge.
// ---------------------------------------------------------------------------
__global__ void __launch_bounds__(256)
qml_bfly_kernel(const float* __restrict__ x, int Btot,
                const float* __restrict__ qw,
                const float* __restrict__ gg, const float* __restrict__ bb,
                const float* __restrict__ rm, const float* __restrict__ rv,
                const float* __restrict__ W1, const float* __restrict__ b1,
                const float* __restrict__ W2, const float* __restrict__ b2,
                float* __restrict__ out) {
    __shared__ float s_gc[16][4];     // per gate: cy, sy, cz, sz
    __shared__ float2 s_ph[DIM];      // layer-1 phase table (permutation-composed)

    const int tid = threadIdx.x;
    const int lane = tid & 31;
    const int warp = tid >> 5;

    if (tid < 16) {
        const float ty = qw[tid * 2 + 0];
        const float tz = qw[tid * 2 + 1];
        float sy, cy, sz, cz;
        sincosf(0.5f * ty, &sy, &cy);
        sincosf(0.5f * tz, &sz, &cz);
        s_gc[tid][0] = cy; s_gc[tid][1] = sy;
        s_gc[tid][2] = cz; s_gc[tid][3] = sz;
    }
    {
        // phase table: entry b holds e^{i theta(sigma(b))}, sigma = layer-1
        // CNOT-chain source permutation: final[b] = pre[sigma(b)].
        int idx = tid;
#pragma unroll
        for (int i = 6; i >= 0; --i) {
            const int cb = 1 << (7 - i), tb = 1 << (6 - i);
            if (idx & cb) idx ^= tb;
        }
        float th = 0.0f;
#pragma unroll
        for (int w = 0; w < 8; ++w) {
            const float htz = 0.5f * qw[w * 2 + 1];   // layer-0 RZ angles
            th += ((idx >> (7 - w)) & 1) ? htz : -htz;
        }
        float sph, cph;
        sincosf(th, &sph, &cph);
        s_ph[tid] = make_float2(cph, sph);
    }
    __syncthreads();

    const int stride = gridDim.x * 8;
    for (int row = blockIdx.x * 8 + warp; row < Btot; row += stride) {
        float ar[8], ai[8];
        const float* xr = x + (size_t)row * DIM + lane;
#pragma unroll
        for (int k = 0; k < 8; ++k) ar[k] = xr[32 * k];

        // ================= LAYER 1 (real) =================
        // RY wires 0..7 (gid = w); RZ deferred to the phase table.
#pragma unroll
        for (int w = 0; w < 8; ++w) {
            const float cy = s_gc[w][0], sy = s_gc[w][1];
            const int bit = 1 << (7 - w);
            if (bit >= 32) {
                const int kb = bit >> 5;
#pragma unroll
                for (int k0 = 0; k0 < 8; ++k0) {
                    if (!(k0 & kb)) {
                        const int k1 = k0 | kb;
                        const float n0 = cy * ar[k0] - sy * ar[k1];
                        const float n1 = sy * ar[k0] + cy * ar[k1];
                        ar[k0] = n0; ar[k1] = n1;
                    }
                }
            } else {
                const float ssy = (lane & bit) ? sy : -sy;
#pragma unroll
                for (int k = 0; k < 8; ++k) {
                    const float pr = __shfl_xor_sync(FULL, ar[k], bit);
                    ar[k] = cy * ar[k] + ssy * pr;
                }
            }
        }
        // CNOT chain (real)
        {
            float t;
            t = ar[4]; ar[4] = ar[6]; ar[6] = t;   // i=0
            t = ar[5]; ar[5] = ar[7]; ar[7] = t;
            t = ar[2]; ar[2] = ar[3]; ar[3] = t;   // i=1
            t = ar[6]; ar[6] = ar[7]; ar[7] = t;
        }
#pragma unroll
        for (int k = 1; k < 8; k += 2)             // i=2
            ar[k] = __shfl_xor_sync(FULL, ar[k], 16);
#pragma unroll
        for (int cb = 16; cb >= 2; cb >>= 1) {     // i=3..6
            const int src = (lane & cb) ? (lane ^ (cb >> 1)) : lane;
#pragma unroll
            for (int k = 0; k < 8; ++k)
                ar[k] = __shfl_sync(FULL, ar[k], src);
        }
        // apply deferred layer-1 phases: a_b *= e^{i theta(sigma(b))}
#pragma unroll
        for (int k = 0; k < 8; ++k) {
            const float2 ph = s_ph[lane + 32 * k];
            const float r = ar[k];
            ar[k] = r * ph.x;
            ai[k] = r * ph.y;
        }

        // ================= LAYER 2 (complex, gid = 8+w) =================
#pragma unroll
        for (int w = 0; w < 8; ++w) {
            const int gid = 8 + w;
            const float cy = s_gc[gid][0], sy = s_gc[gid][1];
            const float cz = s_gc[gid][2], sz = s_gc[gid][3];
            const int bit = 1 << (7 - w);
            if (bit >= 32) {
                const int kb = bit >> 5;
#pragma unroll
                for (int k0 = 0; k0 < 8; ++k0) {
                    if (!(k0 & kb)) {
                        const int k1 = k0 | kb;
                        const float n0r = cy * ar[k0] - sy * ar[k1];
                        const float n0i = cy * ai[k0] - sy * ai[k1];
                        const float n1r = sy * ar[k0] + cy * ar[k1];
                        const float n1i = sy * ai[k0] + cy * ai[k1];
                        ar[k0] = cz * n0r + sz * n0i;
                        ai[k0] = cz * n0i - sz * n0r;
                        ar[k1] = cz * n1r - sz * n1i;
                        ai[k1] = cz * n1i + sz * n1r;
                    }
                }
            } else {
                const float ssy = (lane & bit) ? sy : -sy;
                const float ssz = (lane & bit) ? sz : -sz;
#pragma unroll
                for (int k = 0; k < 8; ++k) {
                    const float pr = __shfl_xor_sync(FULL, ar[k], bit);
                    const float pi = __shfl_xor_sync(FULL, ai[k], bit);
                    const float nr = cy * ar[k] + ssy * pr;
                    const float ni = cy * ai[k] + ssy * pi;
                    ar[k] = cz * nr - ssz * ni;
                    ai[k] = cz * ni + ssz * nr;
                }
            }
        }
        {
            float t;
            t = ar[4]; ar[4] = ar[6]; ar[6] = t;
            t = ai[4]; ai[4] = ai[6]; ai[6] = t;
            t = ar[5]; ar[5] = ar[7]; ar[7] = t;
            t = ai[5]; ai[5] = ai[7]; ai[7] = t;
            t = ar[2]; ar[2] = ar[3]; ar[3] = t;
            t = ai[2]; ai[2] = ai[3]; ai[3] = t;
            t = ar[6]; ar[6] = ar[7]; ar[7] = t;
            t = ai[6]; ai[6] = ai[7]; ai[7] = t;
        }
#pragma unroll
        for (int k = 1; k < 8; k += 2) {
            ar[k] = __shfl_xor_sync(FULL, ar[k], 16);
            ai[k] = __shfl_xor_sync(FULL, ai[k], 16);
        }
#pragma unroll
        for (int cb = 16; cb >= 2; cb >>= 1) {
            const int src = (lane & cb) ? (lane ^ (cb >> 1)) : lane;
#pragma unroll
            for (int k = 0; k < 8; ++k) {
                ar[k] = __shfl_sync(FULL, ar[k], src);
                ai[k] = __shfl_sync(FULL, ai[k], src);
            }
        }

        // ================= expectations =================
        float p[8], psum = 0.0f;
#pragma unroll
        for (int k = 0; k < 8; ++k) {
            p[k] = ar[k] * ar[k] + ai[k] * ai[k];
            psum += p[k];
        }
        float v[11];   // z0,z1,z2, xp0..xp7 (per-lane partials)
        v[0] = (p[0] + p[1] + p[2] + p[3]) - (p[4] + p[5] + p[6] + p[7]);
        v[1] = (p[0] + p[1] + p[4] + p[5]) - (p[2] + p[3] + p[6] + p[7]);
        v[2] = (p[0] + p[2] + p[4] + p[6]) - (p[1] + p[3] + p[5] + p[7]);
        v[3] = v[4] = v[5] = 0.0f;
#pragma unroll
        for (int k = 0; k < 8; ++k) {
            v[5] += ar[k] * ar[k ^ 1] + ai[k] * ai[k ^ 1];  // xp2 (bit 32)
            v[4] += ar[k] * ar[k ^ 2] + ai[k] * ai[k ^ 2];  // xp1 (bit 64)
            v[3] += ar[k] * ar[k ^ 4] + ai[k] * ai[k ^ 4];  // xp0 (bit 128)
        }
#pragma unroll
        for (int i = 0; i < 5; ++i) {   // xp3..xp7 (lane bits 16..1)
            const int bit = 16 >> i;
            float acc = 0.0f;
#pragma unroll
            for (int k = 0; k < 8; ++k) {
                acc += ar[k] * __shfl_xor_sync(FULL, ar[k], bit);
                acc += ai[k] * __shfl_xor_sync(FULL, ai[k], bit);
            }
            v[6 + i] = acc;
        }

        // WHT of psum: lane L ends with sum_l (-1)^{popc(L&l)} psum_l.
        float h = psum;
#pragma unroll
        for (int off = 16; off; off >>= 1) {
            const float t = __shfl_xor_sync(FULL, h, off);
            h = (lane & off) ? (t - h) : (h + t);
        }
        const float norm2 = __shfl_sync(FULL, h, 0);   // total ||y||^2
        float zl[5];                                   // z3..z7
        zl[0] = __shfl_sync(FULL, h, 16);
        zl[1] = __shfl_sync(FULL, h, 8);
        zl[2] = __shfl_sync(FULL, h, 4);
        zl[3] = __shfl_sync(FULL, h, 2);
        zl[4] = __shfl_sync(FULL, h, 1);

        // tree-merge reduction of the 11 plain sums
        const float p0 = merge2(v[0], v[1], 16, lane);
        const float p1 = merge2(v[2], v[3], 16, lane);
        const float p2 = merge2(v[4], v[5], 16, lane);
        const float p3 = merge2(v[6], v[7], 16, lane);
        const float p4 = merge2(v[8], v[9], 16, lane);
        const float p5 = v[10] + __shfl_xor_sync(FULL, v[10], 16);
        const float q0 = merge2(p0, p1, 8, lane);
        const float q1 = merge2(p2, p3, 8, lane);
        const float q2 = merge2(p4, p5, 8, lane);
        const float r0 = merge2(q0, q1, 4, lane);
        const float r1 = q2 + __shfl_xor_sync(FULL, q2, 4);
        float s = merge2(r0, r1, 2, lane);
        s += __shfl_xor_sync(FULL, s, 1);
        // owner lanes: v0:0 v1:16 v2:8 v3:24 v4:4 v5:20 v6:12 v7:28 v8:2 v9:18 v10:10
        float red[11];
        red[0]  = __shfl_sync(FULL, s, 0);
        red[1]  = __shfl_sync(FULL, s, 16);
        red[2]  = __shfl_sync(FULL, s, 8);
        red[3]  = __shfl_sync(FULL, s, 24);
        red[4]  = __shfl_sync(FULL, s, 4);
        red[5]  = __shfl_sync(FULL, s, 20);
        red[6]  = __shfl_sync(FULL, s, 12);
        red[7]  = __shfl_sync(FULL, s, 28);
        red[8]  = __shfl_sync(FULL, s, 2);
        red[9]  = __shfl_sync(FULL, s, 18);
        red[10] = __shfl_sync(FULL, s, 10);

        if (lane == 0) {
            const float inv_n = 1.0f / norm2;
            float q[16];
            q[0] = red[0] * inv_n;   // z0
            q[1] = red[1] * inv_n;   // z1
            q[2] = red[2] * inv_n;   // z2
#pragma unroll
            for (int i = 0; i < 5; ++i) q[3 + i] = zl[i] * inv_n;      // z3..z7
#pragma unroll
            for (int i = 0; i < 8; ++i) q[8 + i] = red[3 + i] * inv_n; // xp0..xp7
            float hbn[16];
#pragma unroll
            for (int i = 0; i < 16; ++i)
                hbn[i] = gg[i] * (q[i] - rm[i]) * rsqrtf(rv[i] + 1e-5f) + bb[i];
            float hh[8];
#pragma unroll
            for (int j = 0; j < 8; ++j) {
                float acc = b1[j];
#pragma unroll
                for (int i = 0; i < 16; ++i) acc += hbn[i] * W1[i * 8 + j];
                hh[j] = fmaxf(acc, 0.0f);
            }
#pragma unroll
            for (int k2 = 0; k2 < 2; ++k2) {
                float acc = b2[k2];
#pragma unroll
                for (int j = 0; j < 8; ++j) acc += hh[j] * W2[j * 2 + k2];
                out[(size_t)row * 2 + k2] = acc;
            }
        }
    }
}

// ---------------------------------------------------------------------------
extern "C" void kernel_launch(void* const* d_in, const int* in_sizes, int n_in,
                              void* d_out, int out_size) {
    const float* x  = (const float*)d_in[0];
    const float* qw = (const float*)d_in[1];
    const float* gg = (const float*)d_in[2];
    const float* bb = (const float*)d_in[3];
    const float* rm = (const float*)d_in[4];
    const float* rv = (const float*)d_in[5];
    const float* W1 = (const float*)d_in[6];
    const float* b1 = (const float*)d_in[7];
    const float* W2 = (const float*)d_in[8];
    const float* b2 = (const float*)d_in[9];
    float* out = (float*)d_out;

    const int Btot = in_sizes[0] / DIM;
    if (Btot <= 0) return;

    qml_bfly_kernel<<<1024, 256>>>(x, Btot, qw, gg, bb, rm, rv,
                                   W1, b1, W2, b2, out);
}

// round 12
// speedup vs baseline: 4.3798x; 1.0567x over previous
#include <cuda_runtime.h>
#include <cstdint>

#define DIM 256
#define FULL 0xffffffffu

__device__ __forceinline__ int par(int v) { return __popc(v) & 1; }

// merge2(a,b,off): lanes with (lane&off)==0 end with a-sum over the off-pair,
// lanes with the bit set end with the b-sum. One shfl per call.
__device__ __forceinline__ float merge2(float a, float b, int off, int lane) {
    const bool sel = (lane & off) != 0;
    const float xv = sel ? b : a;
    const float yv = __shfl_xor_sync(FULL, sel ? a : b, off);
    return xv + yv;
}

// ---------------------------------------------------------------------------
// Warp-per-row direct evolution, CNOT permutations ABSORBED into index algebra.
// Storage index p: lane = p>>3 (bits 7..3), reg r = p&7 (bits 2..0).
// True index = mu(p); mu after L1 CNOT = P^-1, after L2 CNOT = P^-2, where
// P: b_j -> b_j ^ b_{j+1}. All flip/sign masks below derived from that.
// ---------------------------------------------------------------------------
__global__ void __launch_bounds__(256)
qml_bfly_kernel(const float* __restrict__ x, int Btot,
                const float* __restrict__ qw,
                const float* __restrict__ gg, const float* __restrict__ bb,
                const float* __restrict__ rm, const float* __restrict__ rv,
                const float* __restrict__ W1, const float* __restrict__ b1,
                const float* __restrict__ W2, const float* __restrict__ b2,
                float* __restrict__ out) {
    __shared__ float s_gc[16][4];     // per gate: cy, sy, cz, sz
    __shared__ float2 s_ph[DIM];      // layer-1 deferred RZ phases (index = p)

    const int tid = threadIdx.x;
    const int lane = tid & 31;
    const int warp = tid >> 5;
    const int lane_par = par(lane);

    if (tid < 16) {
        const float ty = qw[tid * 2 + 0];
        const float tz = qw[tid * 2 + 1];
        float sy, cy, sz, cz;
        sincosf(0.5f * ty, &sy, &cy);
        sincosf(0.5f * tz, &sz, &cz);
        s_gc[tid][0] = cy; s_gc[tid][1] = sy;
        s_gc[tid][2] = cz; s_gc[tid][3] = sz;
    }
    {
        // theta(p) = sum_w (bit(7-w) of p ? +tz_w/2 : -tz_w/2), layer-0 gates.
        float th = 0.0f;
#pragma unroll
        for (int w = 0; w < 8; ++w) {
            const float htz = 0.5f * qw[w * 2 + 1];
            th += ((tid >> (7 - w)) & 1) ? htz : -htz;
        }
        float sph, cph;
        sincosf(th, &sph, &cph);
        s_ph[tid] = make_float2(cph, sph);
    }
    __syncthreads();

    const int stride = gridDim.x * 8;
    for (int row = blockIdx.x * 8 + warp; row < Btot; row += stride) {
        float ar[8], ai[8];
        {
            const float4* x4 = reinterpret_cast<const float4*>(
                x + (size_t)row * DIM + lane * 8);
            const float4 f0 = x4[0], f1 = x4[1];
            ar[0] = f0.x; ar[1] = f0.y; ar[2] = f0.z; ar[3] = f0.w;
            ar[4] = f1.x; ar[5] = f1.y; ar[6] = f1.z; ar[7] = f1.w;
        }

        // ================= LAYER 1 (real; RZ deferred) =================
        // wires 0..4 -> lane bits 4..0
#pragma unroll
        for (int w = 0; w < 5; ++w) {
            const float cy = s_gc[w][0], sy = s_gc[w][1];
            const int Lm = 1 << (4 - w);
            const float ssy = (lane & Lm) ? sy : -sy;
#pragma unroll
            for (int r = 0; r < 8; ++r) {
                const float pr = __shfl_xor_sync(FULL, ar[r], Lm);
                ar[r] = cy * ar[r] + ssy * pr;
            }
        }
        // wires 5,6,7 -> reg bits 2,1,0 (standard single-bit, real)
#pragma unroll
        for (int w = 5; w < 8; ++w) {
            const float cy = s_gc[w][0], sy = s_gc[w][1];
            const int kb = 1 << (7 - w);
#pragma unroll
            for (int r0 = 0; r0 < 8; ++r0) {
                if (!(r0 & kb)) {
                    const int r1 = r0 | kb;
                    const float n0 = cy * ar[r0] - sy * ar[r1];
                    const float n1 = sy * ar[r0] + cy * ar[r1];
                    ar[r0] = n0; ar[r1] = n1;
                }
            }
        }
        // deferred layer-1 phases (mu = id here)
#pragma unroll
        for (int r = 0; r < 8; ++r) {
            const float2 ph = s_ph[lane * 8 + r];
            const float v = ar[r];
            ar[r] = v * ph.x;
            ai[r] = v * ph.y;
        }

        // ================= LAYER 2 (complex; mu = P^-1) =================
        // v=7..4: lane-only flips 24,12,6,3; sign masks on lanes 16,24,28,30
        {
            const int Lm_[4]  = {24, 12, 6, 3};
            const int Sm_[4]  = {16, 24, 28, 30};
#pragma unroll
            for (int w = 0; w < 4; ++w) {
                const int gid = 8 + w;
                const float cy = s_gc[gid][0], sy = s_gc[gid][1];
                const float cz = s_gc[gid][2], sz = s_gc[gid][3];
                const bool st = par(lane & Sm_[w]);
                const float ssy = st ? sy : -sy;
                const float ssz = st ? sz : -sz;
#pragma unroll
                for (int r = 0; r < 8; ++r) {
                    const float pr = __shfl_xor_sync(FULL, ar[r], Lm_[w]);
                    const float pi = __shfl_xor_sync(FULL, ai[r], Lm_[w]);
                    const float nr = cy * ar[r] + ssy * pr;
                    const float ni = cy * ai[r] + ssy * pi;
                    ar[r] = cz * nr - ssz * ni;
                    ai[r] = cz * ni + ssz * nr;
                }
            }
        }
        // v=3 (w=4): flip = lane^1, reg^4; sign = parity(lane)
        {
            const float cy = s_gc[12][0], sy = s_gc[12][1];
            const float cz = s_gc[12][2], sz = s_gc[12][3];
            const float ssy = lane_par ? sy : -sy;
            const float ssz = lane_par ? sz : -sz;
#pragma unroll
            for (int r = 0; r < 4; ++r) {
                const float p0r = __shfl_xor_sync(FULL, ar[r + 4], 1);
                const float p0i = __shfl_xor_sync(FULL, ai[r + 4], 1);
                const float p1r = __shfl_xor_sync(FULL, ar[r], 1);
                const float p1i = __shfl_xor_sync(FULL, ai[r], 1);
                const float nr0 = cy * ar[r] + ssy * p0r;
                const float ni0 = cy * ai[r] + ssy * p0i;
                const float nr1 = cy * ar[r + 4] + ssy * p1r;
                const float ni1 = cy * ai[r + 4] + ssy * p1i;
                ar[r] = cz * nr0 - ssz * ni0;
                ai[r] = cz * ni0 + ssz * nr0;
                ar[r + 4] = cz * nr1 - ssz * ni1;
                ai[r + 4] = cz * ni1 + ssz * nr1;
            }
        }
        // v=2,1,0 (w=5,6,7): register flips 6,3,1; roles depend on lane parity.
        // c = "rB is set" = (lane_par == 0).
        {
            const bool c = (lane_par == 0);
            const int pairsA[3][4] = {{0, 1, 2, 3}, {0, 1, 6, 7}, {0, 3, 5, 6}};
            const int flips[3] = {6, 3, 1};
#pragma unroll
            for (int w = 5; w < 8; ++w) {
                const int gid = 8 + w;
                const float cy = s_gc[gid][0], sy = s_gc[gid][1];
                const float cz = s_gc[gid][2], sz = s_gc[gid][3];
                const float s1 = c ? sy : -sy;
                const float s2 = c ? sz : -sz;
#pragma unroll
                for (int j = 0; j < 4; ++j) {
                    const int rA = pairsA[w - 5][j];
                    const int rB = rA ^ flips[w - 5];
                    const float nAr = cy * ar[rA] - s1 * ar[rB];
                    const float nAi = cy * ai[rA] - s1 * ai[rB];
                    const float nBr = cy * ar[rB] + s1 * ar[rA];
                    const float nBi = cy * ai[rB] + s1 * ai[rA];
                    ar[rA] = cz * nAr + s2 * nAi;
                    ai[rA] = cz * nAi - s2 * nAr;
                    ar[rB] = cz * nBr - s2 * nBi;
                    ai[rB] = cz * nBi + s2 * nBr;
                }
            }
        }

        // ================= expectations (mu = P^-2) =================
        float p[8], psum = 0.0f;
#pragma unroll
        for (int r = 0; r < 8; ++r) {
            p[r] = ar[r] * ar[r] + ai[r] * ai[r];
            psum += p[r];
        }
        const float Sa = (p[0] + p[1] + p[2] + p[3]) - (p[4] + p[5] + p[6] + p[7]);
        const float Sb = (p[0] + p[1] + p[4] + p[5]) - (p[2] + p[3] + p[6] + p[7]);
        const float Sc = (p[0] + p[2] + p[5] + p[7]) - (p[1] + p[3] + p[4] + p[6]);

        // xp partials: flips P^2 e_i
        float xpp[8];
        xpp[2] = xpp[1] = xpp[0] = 0.0f;
        xpp[7] = xpp[6] = xpp[5] = xpp[4] = xpp[3] = 0.0f;
#pragma unroll
        for (int r = 0; r < 8; ++r) {
            xpp[2] += ar[r] * ar[r ^ 5] + ai[r] * ai[r ^ 5];
            xpp[1] += ar[r] * ar[r ^ 2] + ai[r] * ai[r ^ 2];
            xpp[0] += ar[r] * ar[r ^ 1] + ai[r] * ai[r ^ 1];
            xpp[7] += ar[r] * __shfl_xor_sync(FULL, ar[r], 20)
                    + ai[r] * __shfl_xor_sync(FULL, ai[r], 20);
            xpp[6] += ar[r] * __shfl_xor_sync(FULL, ar[r], 10)
                    + ai[r] * __shfl_xor_sync(FULL, ai[r], 10);
            xpp[5] += ar[r] * __shfl_xor_sync(FULL, ar[r], 5)
                    + ai[r] * __shfl_xor_sync(FULL, ai[r], 5);
            xpp[4] += ar[r] * __shfl_xor_sync(FULL, ar[r ^ 4], 2)
                    + ai[r] * __shfl_xor_sync(FULL, ai[r ^ 4], 2);
            xpp[3] += ar[r] * __shfl_xor_sync(FULL, ar[r ^ 2], 1)
                    + ai[r] * __shfl_xor_sync(FULL, ai[r ^ 2], 1);
        }

        // lane-WHTs of psum, Sa, Sb, Sc
        float w0 = psum, w1 = Sa, w2 = Sb, w3 = Sc;
#pragma unroll
        for (int off = 16; off; off >>= 1) {
            const float t0 = __shfl_xor_sync(FULL, w0, off);
            const float t1 = __shfl_xor_sync(FULL, w1, off);
            const float t2 = __shfl_xor_sync(FULL, w2, off);
            const float t3 = __shfl_xor_sync(FULL, w3, off);
            if (lane & off) { w0 = t0 - w0; w1 = t1 - w1; w2 = t2 - w2; w3 = t3 - w3; }
            else            { w0 = t0 + w0; w1 = t1 + w1; w2 = t2 + w2; w3 = t3 + w3; }
        }
        const float norm2 = __shfl_sync(FULL, w0, 0);
        const float z7 = __shfl_sync(FULL, w0, 16);
        const float z6 = __shfl_sync(FULL, w0, 8);
        const float z5 = __shfl_sync(FULL, w0, 20);
        const float z4 = __shfl_sync(FULL, w0, 10);
        const float z3 = __shfl_sync(FULL, w0, 21);
        const float z2 = __shfl_sync(FULL, w1, 10);
        const float z1 = __shfl_sync(FULL, w2, 21);
        const float z0 = __shfl_sync(FULL, w3, 10);

        // tree-merge the 8 xp sums
        const float m0 = merge2(xpp[0], xpp[1], 16, lane);
        const float m1 = merge2(xpp[2], xpp[3], 16, lane);
        const float m2 = merge2(xpp[4], xpp[5], 16, lane);
        const float m3 = merge2(xpp[6], xpp[7], 16, lane);
        const float q0 = merge2(m0, m1, 8, lane);
        const float q1 = merge2(m2, m3, 8, lane);
        float r0 = merge2(q0, q1, 4, lane);
        r0 += __shfl_xor_sync(FULL, r0, 2);
        r0 += __shfl_xor_sync(FULL, r0, 1);
        const float xv0 = __shfl_sync(FULL, r0, 0);
        const float xv1 = __shfl_sync(FULL, r0, 16);
        const float xv2 = __shfl_sync(FULL, r0, 8);
        const float xv3 = __shfl_sync(FULL, r0, 24);
        const float xv4 = __shfl_sync(FULL, r0, 4);
        const float xv5 = __shfl_sync(FULL, r0, 20);
        const float xv6 = __shfl_sync(FULL, r0, 12);
        const float xv7 = __shfl_sync(FULL, r0, 28);

        if (lane == 0) {
            const float inv_n = 1.0f / norm2;
            float q[16];
            // q[w] = z_{7-w}; q[8+w] = xp_{7-w}
            q[0] = z7 * inv_n; q[1] = z6 * inv_n; q[2] = z5 * inv_n; q[3] = z4 * inv_n;
            q[4] = z3 * inv_n; q[5] = z2 * inv_n; q[6] = z1 * inv_n; q[7] = z0 * inv_n;
            q[8]  = xv7 * inv_n; q[9]  = xv6 * inv_n; q[10] = xv5 * inv_n;
            q[11] = xv4 * inv_n; q[12] = xv3 * inv_n; q[13] = xv2 * inv_n;
            q[14] = xv1 * inv_n; q[15] = xv0 * inv_n;
            float hbn[16];
#pragma unroll
            for (int i = 0; i < 16; ++i)
                hbn[i] = gg[i] * (q[i] - rm[i]) * rsqrtf(rv[i] + 1e-5f) + bb[i];
            float hh[8];
#pragma unroll
            for (int j = 0; j < 8; ++j) {
                float acc = b1[j];
#pragma unroll
                for (int i = 0; i < 16; ++i) acc += hbn[i] * W1[i * 8 + j];
                hh[j] = fmaxf(acc, 0.0f);
            }
#pragma unroll
            for (int k2 = 0; k2 < 2; ++k2) {
                float acc = b2[k2];
#pragma unroll
                for (int j = 0; j < 8; ++j) acc += hh[j] * W2[j * 2 + k2];
                out[(size_t)row * 2 + k2] = acc;
            }
        }
    }
}

// ---------------------------------------------------------------------------
extern "C" void kernel_launch(void* const* d_in, const int* in_sizes, int n_in,
                              void* d_out, int out_size) {
    const float* x  = (const float*)d_in[0];
    const float* qw = (const float*)d_in[1];
    const float* gg = (const float*)d_in[2];
    const float* bb = (const float*)d_in[3];
    const float* rm = (const float*)d_in[4];
    const float* rv = (const float*)d_in[5];
    const float* W1 = (const float*)d_in[6];
    const float* b1 = (const float*)d_in[7];
    const float* W2 = (const float*)d_in[8];
    const float* b2 = (const float*)d_in[9];
    float* out = (float*)d_out;

    const int Btot = in_sizes[0] / DIM;
    if (Btot <= 0) return;

    qml_bfly_kernel<<<1024, 256>>>(x, Btot, qw, gg, bb, rm, rv,
                                   W1, b1, W2, b2, out);
}

// round 13
// speedup vs baseline: 4.7349x; 1.0811x over previous
#include <cuda_runtime.h>
#include <cstdint>

#define DIM 256
#define FULL 0xffffffffu

__device__ __forceinline__ int par(int v) { return __popc(v) & 1; }

// merge2 within 16-lane groups (off <= 8)
__device__ __forceinline__ float merge2(float a, float b, int off, int lane4) {
    const bool sel = (lane4 & off) != 0;
    const float xv = sel ? b : a;
    const float yv = __shfl_xor_sync(FULL, sel ? a : b, off);
    return xv + yv;
}

// ---------------------------------------------------------------------------
// 16 lanes per row (2 rows per warp). Storage index p: lane4 = p>>4 (bits
// 7..4), reg r = p&15 (bits 3..0). CNOT chains absorbed: layer-2 under
// mu=P^-1 (true bit v = par(p>>v)), expectations under mu=P^-2 (true bit v =
// par(p & {v,v+2,...})). Flips: layer {v,v-1}; xp {v,v-2}.
// ---------------------------------------------------------------------------
__global__ void __launch_bounds__(256)
qml_bfly_kernel(const float* __restrict__ x, int Btot,
                const float* __restrict__ qw,
                const float* __restrict__ gg, const float* __restrict__ bb,
                const float* __restrict__ rm, const float* __restrict__ rv,
                const float* __restrict__ W1, const float* __restrict__ b1,
                const float* __restrict__ W2, const float* __restrict__ b2,
                float* __restrict__ out) {
    __shared__ float s_gc[16][4];     // per gate: cy, sy, cz, sz
    __shared__ float2 s_ph[DIM];      // layer-1 deferred RZ phases (index p)

    const int tid = threadIdx.x;
    const int lane = tid & 31;
    const int warp = tid >> 5;
    const int lane4 = lane & 15;
    const int half = lane >> 4;
    const int l4par = par(lane4);

    if (tid < 16) {
        const float ty = qw[tid * 2 + 0];
        const float tz = qw[tid * 2 + 1];
        float sy, cy, sz, cz;
        sincosf(0.5f * ty, &sy, &cy);
        sincosf(0.5f * tz, &sz, &cz);
        s_gc[tid][0] = cy; s_gc[tid][1] = sy;
        s_gc[tid][2] = cz; s_gc[tid][3] = sz;
    }
    {
        float th = 0.0f;
#pragma unroll
        for (int w = 0; w < 8; ++w) {
            const float htz = 0.5f * qw[w * 2 + 1];
            th += ((tid >> (7 - w)) & 1) ? htz : -htz;
        }
        float sph, cph;
        sincosf(th, &sph, &cph);
        s_ph[tid] = make_float2(cph, sph);
    }
    __syncthreads();

    const int stride = gridDim.x * 16;
    for (int row = blockIdx.x * 16 + warp * 2 + half; row - half < Btot; row += stride) {
        const bool valid = row < Btot;
        float ar[16], ai[16];
        {
            const float4* x4 = reinterpret_cast<const float4*>(
                x + (size_t)(valid ? row : 0) * DIM + lane4 * 16);
#pragma unroll
            for (int j = 0; j < 4; ++j) {
                const float4 f = valid ? x4[j] : make_float4(0, 0, 0, 0);
                ar[j * 4 + 0] = f.x; ar[j * 4 + 1] = f.y;
                ar[j * 4 + 2] = f.z; ar[j * 4 + 3] = f.w;
            }
        }

        // ================= LAYER 1 (real; RZ deferred) =================
        // wires 0..3 -> lane bits 3..0 of lane4 (true bits 7..4)
#pragma unroll
        for (int w = 0; w < 4; ++w) {
            const float cy = s_gc[w][0], sy = s_gc[w][1];
            const int Lm = 1 << (3 - w);
            const float ssy = (lane4 & Lm) ? sy : -sy;
#pragma unroll
            for (int r = 0; r < 16; ++r) {
                const float pr = __shfl_xor_sync(FULL, ar[r], Lm);
                ar[r] = cy * ar[r] + ssy * pr;
            }
        }
        // wires 4..7 -> reg bits 3..0 (standard real butterflies)
#pragma unroll
        for (int w = 4; w < 8; ++w) {
            const float cy = s_gc[w][0], sy = s_gc[w][1];
            const int kb = 1 << (7 - w);
#pragma unroll
            for (int r0 = 0; r0 < 16; ++r0) {
                if (!(r0 & kb)) {
                    const int r1 = r0 | kb;
                    const float n0 = cy * ar[r0] - sy * ar[r1];
                    const float n1 = sy * ar[r0] + cy * ar[r1];
                    ar[r0] = n0; ar[r1] = n1;
                }
            }
        }
        // deferred layer-1 phases
#pragma unroll
        for (int r = 0; r < 16; ++r) {
            const float2 ph = s_ph[lane4 * 16 + r];
            const float v = ar[r];
            ar[r] = v * ph.x;
            ai[r] = v * ph.y;
        }

        // ================= LAYER 2 (complex; mu = P^-1) =================
        // v=7,6,5: pure lane flips {12,6,3}; sign = par(lane4 & {8,12,14})
        {
            const int Lm_[3] = {12, 6, 3};
            const int Sm_[3] = {8, 12, 14};
#pragma unroll
            for (int w = 0; w < 3; ++w) {
                const int gid = 8 + w;
                const float cy = s_gc[gid][0], sy = s_gc[gid][1];
                const float cz = s_gc[gid][2], sz = s_gc[gid][3];
                const bool st = par(lane4 & Sm_[w]);
                const float ssy = st ? sy : -sy;
                const float ssz = st ? sz : -sz;
#pragma unroll
                for (int r = 0; r < 16; ++r) {
                    const float pr = __shfl_xor_sync(FULL, ar[r], Lm_[w]);
                    const float pi = __shfl_xor_sync(FULL, ai[r], Lm_[w]);
                    const float nr = cy * ar[r] + ssy * pr;
                    const float ni = cy * ai[r] + ssy * pi;
                    ar[r] = cz * nr - ssz * ni;
                    ai[r] = cz * ni + ssz * nr;
                }
            }
        }
        // v=4 (gid=11): flip lane^1, reg^8; sign = par(lane4)
        {
            const float cy = s_gc[11][0], sy = s_gc[11][1];
            const float cz = s_gc[11][2], sz = s_gc[11][3];
            const float ssy = l4par ? sy : -sy;
            const float ssz = l4par ? sz : -sz;
#pragma unroll
            for (int r = 0; r < 8; ++r) {
                const float p0r = __shfl_xor_sync(FULL, ar[r + 8], 1);
                const float p0i = __shfl_xor_sync(FULL, ai[r + 8], 1);
                const float p1r = __shfl_xor_sync(FULL, ar[r], 1);
                const float p1i = __shfl_xor_sync(FULL, ai[r], 1);
                const float nr0 = cy * ar[r] + ssy * p0r;
                const float ni0 = cy * ai[r] + ssy * p0i;
                const float nr1 = cy * ar[r + 8] + ssy * p1r;
                const float ni1 = cy * ai[r + 8] + ssy * p1i;
                ar[r] = cz * nr0 - ssz * ni0;
                ai[r] = cz * ni0 + ssz * nr0;
                ar[r + 8] = cz * nr1 - ssz * ni1;
                ai[r + 8] = cz * ni1 + ssz * nr1;
            }
        }
        // v=3..0 (gid=12..15): reg flips {12,6,3,1}; rA = regs with
        // par(r & S_reg)==0 (S_reg = {8,12,14,15}); role c = (par(lane4)==0)
        {
            const bool c = (l4par == 0);
            const int pairsA[4][8] = {
                {0, 1, 2, 3, 4, 5, 6, 7},        // v=3, F=12
                {0, 1, 2, 3, 12, 13, 14, 15},    // v=2, F=6
                {0, 1, 6, 7, 10, 11, 12, 13},    // v=1, F=3
                {0, 3, 5, 6, 9, 10, 12, 15}      // v=0, F=1
            };
            const int flips[4] = {12, 6, 3, 1};
#pragma unroll
            for (int w = 0; w < 4; ++w) {
                const int gid = 12 + w;
                const float cy = s_gc[gid][0], sy = s_gc[gid][1];
                const float cz = s_gc[gid][2], sz = s_gc[gid][3];
                const float s1 = c ? sy : -sy;
                const float s2 = c ? sz : -sz;
#pragma unroll
                for (int j = 0; j < 8; ++j) {
                    const int rA = pairsA[w][j];
                    const int rB = rA ^ flips[w];
                    const float nAr = cy * ar[rA] - s1 * ar[rB];
                    const float nAi = cy * ai[rA] - s1 * ai[rB];
                    const float nBr = cy * ar[rB] + s1 * ar[rA];
                    const float nBi = cy * ai[rB] + s1 * ai[rA];
                    ar[rA] = cz * nAr + s2 * nAi;
                    ai[rA] = cz * nAi - s2 * nAr;
                    ar[rB] = cz * nBr - s2 * nBi;
                    ai[rB] = cz * nBi + s2 * nBr;
                }
            }
        }

        // ================= expectations (mu = P^-2) =================
        float p[16], psum = 0.0f;
#pragma unroll
        for (int r = 0; r < 16; ++r) {
            p[r] = ar[r] * ar[r] + ai[r] * ai[r];
            psum += p[r];
        }
        // reg-signed sums for z with reg-components
        float S8 = 0.0f, S4m = 0.0f, S10 = 0.0f, S5m = 0.0f;
#pragma unroll
        for (int r = 0; r < 16; ++r) {
            S8  += par(r & 8)  ? -p[r] : p[r];
            S4m += par(r & 4)  ? -p[r] : p[r];
            S10 += par(r & 10) ? -p[r] : p[r];
            S5m += par(r & 5)  ? -p[r] : p[r];
        }

        // xp partials: masks {v, v-2} in storage coords
        float x7p = 0.0f, x6p = 0.0f, x5p = 0.0f, x4p = 0.0f;
        float x3p = 0.0f, x2p = 0.0f, x1p = 0.0f, x0p = 0.0f;
#pragma unroll
        for (int r = 0; r < 16; ++r) {
            x3p += ar[r] * ar[r ^ 10] + ai[r] * ai[r ^ 10];
            x2p += ar[r] * ar[r ^ 5] + ai[r] * ai[r ^ 5];
            x1p += ar[r] * ar[r ^ 2] + ai[r] * ai[r ^ 2];
            x0p += ar[r] * ar[r ^ 1] + ai[r] * ai[r ^ 1];
            x7p += ar[r] * __shfl_xor_sync(FULL, ar[r], 10)
                 + ai[r] * __shfl_xor_sync(FULL, ai[r], 10);
            x6p += ar[r] * __shfl_xor_sync(FULL, ar[r], 5)
                 + ai[r] * __shfl_xor_sync(FULL, ai[r], 5);
            x5p += ar[r] * __shfl_xor_sync(FULL, ar[r ^ 8], 2)
                 + ai[r] * __shfl_xor_sync(FULL, ai[r ^ 8], 2);
            x4p += ar[r] * __shfl_xor_sync(FULL, ar[r ^ 4], 1)
                 + ai[r] * __shfl_xor_sync(FULL, ai[r ^ 4], 1);
        }

        // 4-stage lane-WHTs (within 16-lane group) of psum, S8, S4m, S10, S5m
        float w0 = psum, w1 = S8, w2 = S4m, w3 = S10, w4 = S5m;
#pragma unroll
        for (int off = 8; off; off >>= 1) {
            const float t0 = __shfl_xor_sync(FULL, w0, off);
            const float t1 = __shfl_xor_sync(FULL, w1, off);
            const float t2 = __shfl_xor_sync(FULL, w2, off);
            const float t3 = __shfl_xor_sync(FULL, w3, off);
            const float t4 = __shfl_xor_sync(FULL, w4, off);
            if (lane4 & off) { w0 = t0 - w0; w1 = t1 - w1; w2 = t2 - w2; w3 = t3 - w3; w4 = t4 - w4; }
            else             { w0 = t0 + w0; w1 = t1 + w1; w2 = t2 + w2; w3 = t3 + w3; w4 = t4 + w4; }
        }
        const int gb = lane & 16;   // group base for gathers
        const float norm2 = __shfl_sync(FULL, w0, gb | 0);
        const float z7 = __shfl_sync(FULL, w0, gb | 8);
        const float z6 = __shfl_sync(FULL, w0, gb | 4);
        const float z5 = __shfl_sync(FULL, w0, gb | 10);
        const float z4 = __shfl_sync(FULL, w0, gb | 5);
        const float z3 = __shfl_sync(FULL, w1, gb | 10);
        const float z2 = __shfl_sync(FULL, w2, gb | 5);
        const float z1 = __shfl_sync(FULL, w3, gb | 10);
        const float z0 = __shfl_sync(FULL, w4, gb | 5);

        // tree-merge the 8 xp sums within the 16-lane group
        const float m0 = merge2(x7p, x6p, 8, lane4);
        const float m1 = merge2(x5p, x4p, 8, lane4);
        const float m2 = merge2(x3p, x2p, 8, lane4);
        const float m3 = merge2(x1p, x0p, 8, lane4);
        const float q0 = merge2(m0, m1, 4, lane4);
        const float q1 = merge2(m2, m3, 4, lane4);
        float r0 = merge2(q0, q1, 2, lane4);
        r0 += __shfl_xor_sync(FULL, r0, 1);
        const float xv7 = __shfl_sync(FULL, r0, gb | 0);
        const float xv6 = __shfl_sync(FULL, r0, gb | 8);
        const float xv5 = __shfl_sync(FULL, r0, gb | 4);
        const float xv4 = __shfl_sync(FULL, r0, gb | 12);
        const float xv3 = __shfl_sync(FULL, r0, gb | 2);
        const float xv2 = __shfl_sync(FULL, r0, gb | 10);
        const float xv1 = __shfl_sync(FULL, r0, gb | 6);
        const float xv0 = __shfl_sync(FULL, r0, gb | 14);

        if (lane4 == 0 && valid) {
            const float inv_n = 1.0f / norm2;
            float q[16];
            q[0] = z7 * inv_n; q[1] = z6 * inv_n; q[2] = z5 * inv_n; q[3] = z4 * inv_n;
            q[4] = z3 * inv_n; q[5] = z2 * inv_n; q[6] = z1 * inv_n; q[7] = z0 * inv_n;
            q[8]  = xv7 * inv_n; q[9]  = xv6 * inv_n; q[10] = xv5 * inv_n;
            q[11] = xv4 * inv_n; q[12] = xv3 * inv_n; q[13] = xv2 * inv_n;
            q[14] = xv1 * inv_n; q[15] = xv0 * inv_n;
            float hbn[16];
#pragma unroll
            for (int i = 0; i < 16; ++i)
                hbn[i] = gg[i] * (q[i] - rm[i]) * rsqrtf(rv[i] + 1e-5f) + bb[i];
            float hh[8];
#pragma unroll
            for (int j = 0; j < 8; ++j) {
                float acc = b1[j];
#pragma unroll
                for (int i = 0; i < 16; ++i) acc += hbn[i] * W1[i * 8 + j];
                hh[j] = fmaxf(acc, 0.0f);
            }
#pragma unroll
            for (int k2 = 0; k2 < 2; ++k2) {
                float acc = b2[k2];
#pragma unroll
                for (int j = 0; j < 8; ++j) acc += hh[j] * W2[j * 2 + k2];
                out[(size_t)row * 2 + k2] = acc;
            }
        }
    }
}

// ---------------------------------------------------------------------------
extern "C" void kernel_launch(void* const* d_in, const int* in_sizes, int n_in,
                              void* d_out, int out_size) {
    const float* x  = (const float*)d_in[0];
    const float* qw = (const float*)d_in[1];
    const float* gg = (const float*)d_in[2];
    const float* bb = (const float*)d_in[3];
    const float* rm = (const float*)d_in[4];
    const float* rv = (const float*)d_in[5];
    const float* W1 = (const float*)d_in[6];
    const float* b1 = (const float*)d_in[7];
    const float* W2 = (const float*)d_in[8];
    const float* b2 = (const float*)d_in[9];
    float* out = (float*)d_out;

    const int Btot = in_sizes[0] / DIM;
    if (Btot <= 0) return;

    qml_bfly_kernel<<<1024, 256>>>(x, Btot, qw, gg, bb, rm, rv,
                                   W1, b1, W2, b2, out);
}

// round 14
// speedup vs baseline: 5.3454x; 1.1289x over previous
#include <cuda_runtime.h>
#include <cstdint>

#define DIM 256
#define FULL 0xffffffffu
typedef unsigned long long ull;
#define NEGM 0x8000000080000000ULL

__device__ __forceinline__ int par(int v) { return __popc(v) & 1; }

__device__ __forceinline__ ull pk(float a, float b) {
    ull d; asm("mov.b64 %0, {%1, %2};" : "=l"(d) : "f"(a), "f"(b)); return d;
}
__device__ __forceinline__ ull pk2(float s) { return pk(s, s); }
__device__ __forceinline__ float2 upk(ull v) {
    float a, b; asm("mov.b64 {%0, %1}, %2;" : "=f"(a), "=f"(b) : "l"(v));
    return make_float2(a, b);
}
__device__ __forceinline__ ull f2mul(ull a, ull b) {
    ull d; asm("mul.rn.f32x2 %0, %1, %2;" : "=l"(d) : "l"(a), "l"(b)); return d;
}
__device__ __forceinline__ ull f2add(ull a, ull b) {
    ull d; asm("add.rn.f32x2 %0, %1, %2;" : "=l"(d) : "l"(a), "l"(b)); return d;
}
__device__ __forceinline__ ull f2fma(ull a, ull b, ull c) {
    ull d; asm("fma.rn.f32x2 %0, %1, %2, %3;" : "=l"(d) : "l"(a), "l"(b), "l"(c)); return d;
}

// packed merge within 16-lane groups
__device__ __forceinline__ ull merge2p(ull a, ull b, int off, int lane4) {
    const bool sel = (lane4 & off) != 0;
    const ull xv = sel ? b : a;
    const ull yv = __shfl_xor_sync(FULL, sel ? a : b, off);
    return f2add(xv, yv);
}

// ---------------------------------------------------------------------------
// R13 layout + index algebra, f32x2-packed over ROW PAIRS.
// 16 lanes per row-pair (2 groups/warp -> 4 rows/warp). Storage index p:
// lane4 = p>>4, reg r = p&15. Layer-2 under mu=P^-1, expectations under
// mu=P^-2 (masks identical to the round-13-verified kernel).
// ---------------------------------------------------------------------------
__global__ void __launch_bounds__(256)
qml_bfly_kernel(const float* __restrict__ x, int Btot,
                const float* __restrict__ qw,
                const float* __restrict__ gg, const float* __restrict__ bb,
                const float* __restrict__ rm, const float* __restrict__ rv,
                const float* __restrict__ W1, const float* __restrict__ b1,
                const float* __restrict__ W2, const float* __restrict__ b2,
                float* __restrict__ out) {
    __shared__ float s_gc[16][4];
    __shared__ ull s_phc[DIM], s_phs[DIM];

    const int tid = threadIdx.x;
    const int lane = tid & 31;
    const int warp = tid >> 5;
    const int lane4 = lane & 15;
    const int half = lane >> 4;
    const int l4par = par(lane4);
    const int gb = lane & 16;

    if (tid < 16) {
        const float ty = qw[tid * 2 + 0];
        const float tz = qw[tid * 2 + 1];
        float sy, cy, sz, cz;
        sincosf(0.5f * ty, &sy, &cy);
        sincosf(0.5f * tz, &sz, &cz);
        s_gc[tid][0] = cy; s_gc[tid][1] = sy;
        s_gc[tid][2] = cz; s_gc[tid][3] = sz;
    }
    {
        float th = 0.0f;
#pragma unroll
        for (int w = 0; w < 8; ++w) {
            const float htz = 0.5f * qw[w * 2 + 1];
            th += ((tid >> (7 - w)) & 1) ? htz : -htz;
        }
        float sph, cph;
        sincosf(th, &sph, &cph);
        s_phc[tid] = pk2(cph);
        s_phs[tid] = pk2(sph);
    }
    __syncthreads();

    const int stride = gridDim.x * 32;
    for (int rb = blockIdx.x * 32 + warp * 4 + half * 2; rb < Btot; rb += stride) {
        const bool v0 = rb < Btot, v1 = rb + 1 < Btot;
        ull ar[16], ai[16];
        {
            const float4* xa = reinterpret_cast<const float4*>(
                x + (size_t)(v0 ? rb : 0) * DIM + lane4 * 16);
            const float4* xb = reinterpret_cast<const float4*>(
                x + (size_t)(v1 ? rb + 1 : 0) * DIM + lane4 * 16);
#pragma unroll
            for (int j = 0; j < 4; ++j) {
                const float4 A = v0 ? xa[j] : make_float4(0, 0, 0, 0);
                const float4 B = v1 ? xb[j] : make_float4(0, 0, 0, 0);
                ar[j * 4 + 0] = pk(A.x, B.x);
                ar[j * 4 + 1] = pk(A.y, B.y);
                ar[j * 4 + 2] = pk(A.z, B.z);
                ar[j * 4 + 3] = pk(A.w, B.w);
            }
        }

        // ========== LAYER 1 (real; RZ deferred) ==========
#pragma unroll
        for (int w = 0; w < 4; ++w) {
            const int Lm = 8 >> w;
            const ull cyP = pk2(s_gc[w][0]);
            ull ssyP = pk2(s_gc[w][1]);
            if (!(lane4 & Lm)) ssyP ^= NEGM;
#pragma unroll
            for (int r = 0; r < 16; ++r) {
                const ull pr = __shfl_xor_sync(FULL, ar[r], Lm);
                ar[r] = f2fma(ssyP, pr, f2mul(cyP, ar[r]));
            }
        }
#pragma unroll
        for (int w = 4; w < 8; ++w) {
            const int kb = 1 << (7 - w);
            const ull cyP = pk2(s_gc[w][0]);
            const ull syP = pk2(s_gc[w][1]);
            const ull nsyP = syP ^ NEGM;
#pragma unroll
            for (int r0 = 0; r0 < 16; ++r0) {
                if (!(r0 & kb)) {
                    const int r1 = r0 | kb;
                    const ull n0 = f2fma(nsyP, ar[r1], f2mul(cyP, ar[r0]));
                    const ull n1 = f2fma(syP, ar[r0], f2mul(cyP, ar[r1]));
                    ar[r0] = n0; ar[r1] = n1;
                }
            }
        }
        // deferred layer-1 phases
#pragma unroll
        for (int r = 0; r < 16; ++r) {
            const ull c = s_phc[lane4 * 16 + r];
            const ull s = s_phs[lane4 * 16 + r];
            ai[r] = f2mul(ar[r], s);
            ar[r] = f2mul(ar[r], c);
        }

        // ========== LAYER 2 (complex; mu = P^-1) ==========
        {
            const int Lm_[3] = {12, 6, 3};
            const int Sm_[3] = {8, 12, 14};
#pragma unroll
            for (int w = 0; w < 3; ++w) {
                const int gid = 8 + w;
                const bool st = par(lane4 & Sm_[w]);
                const ull cyP = pk2(s_gc[gid][0]);
                const ull czP = pk2(s_gc[gid][2]);
                ull ssyP = pk2(s_gc[gid][1]);
                ull sszP = pk2(s_gc[gid][3]);
                if (!st) { ssyP ^= NEGM; sszP ^= NEGM; }
                const ull nsszP = sszP ^ NEGM;
#pragma unroll
                for (int r = 0; r < 16; ++r) {
                    const ull pr = __shfl_xor_sync(FULL, ar[r], Lm_[w]);
                    const ull pi = __shfl_xor_sync(FULL, ai[r], Lm_[w]);
                    const ull nr = f2fma(ssyP, pr, f2mul(cyP, ar[r]));
                    const ull ni = f2fma(ssyP, pi, f2mul(cyP, ai[r]));
                    ar[r] = f2fma(nsszP, ni, f2mul(czP, nr));
                    ai[r] = f2fma(sszP, nr, f2mul(czP, ni));
                }
            }
        }
        // v=4 (gid 11): flip lane^1, reg^8; sign = par(lane4)
        {
            const ull cyP = pk2(s_gc[11][0]);
            const ull czP = pk2(s_gc[11][2]);
            ull ssyP = pk2(s_gc[11][1]);
            ull sszP = pk2(s_gc[11][3]);
            if (!l4par) { ssyP ^= NEGM; sszP ^= NEGM; }
            const ull nsszP = sszP ^ NEGM;
#pragma unroll
            for (int r = 0; r < 8; ++r) {
                const ull p0r = __shfl_xor_sync(FULL, ar[r + 8], 1);
                const ull p0i = __shfl_xor_sync(FULL, ai[r + 8], 1);
                const ull p1r = __shfl_xor_sync(FULL, ar[r], 1);
                const ull p1i = __shfl_xor_sync(FULL, ai[r], 1);
                const ull nr0 = f2fma(ssyP, p0r, f2mul(cyP, ar[r]));
                const ull ni0 = f2fma(ssyP, p0i, f2mul(cyP, ai[r]));
                const ull nr1 = f2fma(ssyP, p1r, f2mul(cyP, ar[r + 8]));
                const ull ni1 = f2fma(ssyP, p1i, f2mul(cyP, ai[r + 8]));
                ar[r] = f2fma(nsszP, ni0, f2mul(czP, nr0));
                ai[r] = f2fma(sszP, nr0, f2mul(czP, ni0));
                ar[r + 8] = f2fma(nsszP, ni1, f2mul(czP, nr1));
                ai[r + 8] = f2fma(sszP, nr1, f2mul(czP, ni1));
            }
        }
        // v=3..0 (gid 12..15): reg flips; role c = (par(lane4)==0)
        {
            const bool c = (l4par == 0);
            const int pairsA[4][8] = {
                {0, 1, 2, 3, 4, 5, 6, 7},
                {0, 1, 2, 3, 12, 13, 14, 15},
                {0, 1, 6, 7, 10, 11, 12, 13},
                {0, 3, 5, 6, 9, 10, 12, 15}
            };
            const int flips[4] = {12, 6, 3, 1};
#pragma unroll
            for (int w = 0; w < 4; ++w) {
                const int gid = 12 + w;
                const ull cyP = pk2(s_gc[gid][0]);
                const ull czP = pk2(s_gc[gid][2]);
                ull s1P = pk2(s_gc[gid][1]);
                ull s2P = pk2(s_gc[gid][3]);
                if (!c) { s1P ^= NEGM; s2P ^= NEGM; }
                const ull ns1P = s1P ^ NEGM;
                const ull ns2P = s2P ^ NEGM;
#pragma unroll
                for (int j = 0; j < 8; ++j) {
                    const int rA = pairsA[w][j];
                    const int rB = rA ^ flips[w];
                    const ull nAr = f2fma(ns1P, ar[rB], f2mul(cyP, ar[rA]));
                    const ull nAi = f2fma(ns1P, ai[rB], f2mul(cyP, ai[rA]));
                    const ull nBr = f2fma(s1P, ar[rA], f2mul(cyP, ar[rB]));
                    const ull nBi = f2fma(s1P, ai[rA], f2mul(cyP, ai[rB]));
                    ar[rA] = f2fma(s2P, nAi, f2mul(czP, nAr));
                    ai[rA] = f2fma(ns2P, nAr, f2mul(czP, nAi));
                    ar[rB] = f2fma(ns2P, nBi, f2mul(czP, nBr));
                    ai[rB] = f2fma(s2P, nBr, f2mul(czP, nBi));
                }
            }
        }

        // ========== expectations (mu = P^-2) ==========
        ull psum = 0ull, S8 = 0ull, S4m = 0ull, S10 = 0ull, S5m = 0ull;
#pragma unroll
        for (int r = 0; r < 16; ++r) {
            const ull pr_ = f2fma(ai[r], ai[r], f2mul(ar[r], ar[r]));
            psum = f2add(psum, pr_);
            S8  = f2add(S8,  par(r & 8)  ? (pr_ ^ NEGM) : pr_);
            S4m = f2add(S4m, par(r & 4)  ? (pr_ ^ NEGM) : pr_);
            S10 = f2add(S10, par(r & 10) ? (pr_ ^ NEGM) : pr_);
            S5m = f2add(S5m, par(r & 5)  ? (pr_ ^ NEGM) : pr_);
        }

        ull x7p = 0ull, x6p = 0ull, x5p = 0ull, x4p = 0ull;
        ull x3p = 0ull, x2p = 0ull, x1p = 0ull, x0p = 0ull;
#pragma unroll
        for (int r = 0; r < 16; ++r) {
            x3p = f2fma(ai[r], ai[r ^ 10], f2fma(ar[r], ar[r ^ 10], x3p));
            x2p = f2fma(ai[r], ai[r ^ 5], f2fma(ar[r], ar[r ^ 5], x2p));
            x1p = f2fma(ai[r], ai[r ^ 2], f2fma(ar[r], ar[r ^ 2], x1p));
            x0p = f2fma(ai[r], ai[r ^ 1], f2fma(ar[r], ar[r ^ 1], x0p));
            x7p = f2fma(ar[r], __shfl_xor_sync(FULL, ar[r], 10), x7p);
            x7p = f2fma(ai[r], __shfl_xor_sync(FULL, ai[r], 10), x7p);
            x6p = f2fma(ar[r], __shfl_xor_sync(FULL, ar[r], 5), x6p);
            x6p = f2fma(ai[r], __shfl_xor_sync(FULL, ai[r], 5), x6p);
            x5p = f2fma(ar[r], __shfl_xor_sync(FULL, ar[r ^ 8], 2), x5p);
            x5p = f2fma(ai[r], __shfl_xor_sync(FULL, ai[r ^ 8], 2), x5p);
            x4p = f2fma(ar[r], __shfl_xor_sync(FULL, ar[r ^ 4], 1), x4p);
            x4p = f2fma(ai[r], __shfl_xor_sync(FULL, ai[r ^ 4], 1), x4p);
        }

        // 4-stage lane-WHTs (packed, cond-negate via xor)
        ull w0 = psum, w1 = S8, w2 = S4m, w3 = S10, w4 = S5m;
#pragma unroll
        for (int off = 8; off; off >>= 1) {
            const ull nm = (lane4 & off) ? NEGM : 0ull;
            const ull t0 = __shfl_xor_sync(FULL, w0, off);
            const ull t1 = __shfl_xor_sync(FULL, w1, off);
            const ull t2 = __shfl_xor_sync(FULL, w2, off);
            const ull t3 = __shfl_xor_sync(FULL, w3, off);
            const ull t4 = __shfl_xor_sync(FULL, w4, off);
            w0 = f2add(t0, w0 ^ nm);
            w1 = f2add(t1, w1 ^ nm);
            w2 = f2add(t2, w2 ^ nm);
            w3 = f2add(t3, w3 ^ nm);
            w4 = f2add(t4, w4 ^ nm);
        }
        const ull normP = __shfl_sync(FULL, w0, gb | 0);
        const ull z7P = __shfl_sync(FULL, w0, gb | 8);
        const ull z6P = __shfl_sync(FULL, w0, gb | 4);
        const ull z5P = __shfl_sync(FULL, w0, gb | 10);
        const ull z4P = __shfl_sync(FULL, w0, gb | 5);
        const ull z3P = __shfl_sync(FULL, w1, gb | 10);
        const ull z2P = __shfl_sync(FULL, w2, gb | 5);
        const ull z1P = __shfl_sync(FULL, w3, gb | 10);
        const ull z0P = __shfl_sync(FULL, w4, gb | 5);

        const ull m0 = merge2p(x7p, x6p, 8, lane4);
        const ull m1 = merge2p(x5p, x4p, 8, lane4);
        const ull m2 = merge2p(x3p, x2p, 8, lane4);
        const ull m3 = merge2p(x1p, x0p, 8, lane4);
        const ull q0 = merge2p(m0, m1, 4, lane4);
        const ull q1 = merge2p(m2, m3, 4, lane4);
        ull r0 = merge2p(q0, q1, 2, lane4);
        r0 = f2add(r0, __shfl_xor_sync(FULL, r0, 1));
        const ull xv7P = __shfl_sync(FULL, r0, gb | 0);
        const ull xv6P = __shfl_sync(FULL, r0, gb | 8);
        const ull xv5P = __shfl_sync(FULL, r0, gb | 4);
        const ull xv4P = __shfl_sync(FULL, r0, gb | 12);
        const ull xv3P = __shfl_sync(FULL, r0, gb | 2);
        const ull xv2P = __shfl_sync(FULL, r0, gb | 10);
        const ull xv1P = __shfl_sync(FULL, r0, gb | 6);
        const ull xv0P = __shfl_sync(FULL, r0, gb | 14);

        // writers: lane4==0 -> row rb (.x), lane4==1 -> row rb+1 (.y)
        const int wrow = rb + lane4;
        if (lane4 < 2 && wrow < Btot) {
            const bool hi = (lane4 == 1);
            const float2 nu = upk(normP);
            const float inv_n = 1.0f / (hi ? nu.y : nu.x);
            const ull zp[8]  = {z7P, z6P, z5P, z4P, z3P, z2P, z1P, z0P};
            const ull xpv[8] = {xv7P, xv6P, xv5P, xv4P, xv3P, xv2P, xv1P, xv0P};
            float q[16];
#pragma unroll
            for (int i = 0; i < 8; ++i) {
                const float2 a = upk(zp[i]);
                const float2 b = upk(xpv[i]);
                q[i]     = (hi ? a.y : a.x) * inv_n;
                q[8 + i] = (hi ? b.y : b.x) * inv_n;
            }
            float hbn[16];
#pragma unroll
            for (int i = 0; i < 16; ++i)
                hbn[i] = gg[i] * (q[i] - rm[i]) * rsqrtf(rv[i] + 1e-5f) + bb[i];
            float hh[8];
#pragma unroll
            for (int j = 0; j < 8; ++j) {
                float acc = b1[j];
#pragma unroll
                for (int i = 0; i < 16; ++i) acc += hbn[i] * W1[i * 8 + j];
                hh[j] = fmaxf(acc, 0.0f);
            }
#pragma unroll
            for (int k2 = 0; k2 < 2; ++k2) {
                float acc = b2[k2];
#pragma unroll
                for (int j = 0; j < 8; ++j) acc += hh[j] * W2[j * 2 + k2];
                out[(size_t)wrow * 2 + k2] = acc;
            }
        }
    }
}

// ---------------------------------------------------------------------------
extern "C" void kernel_launch(void* const* d_in, const int* in_sizes, int n_in,
                              void* d_out, int out_size) {
    const float* x  = (const float*)d_in[0];
    const float* qw = (const float*)d_in[1];
    const float* gg = (const float*)d_in[2];
    const float* bb = (const float*)d_in[3];
    const float* rm = (const float*)d_in[4];
    const float* rv = (const float*)d_in[5];
    const float* W1 = (const float*)d_in[6];
    const float* b1 = (const float*)d_in[7];
    const float* W2 = (const float*)d_in[8];
    const float* b2 = (const float*)d_in[9];
    float* out = (float*)d_out;

    const int Btot = in_sizes[0] / DIM;
    if (Btot <= 0) return;

    qml_bfly_kernel<<<2048, 256>>>(x, Btot, qw, gg, bb, rm, rv,
                                   W1, b1, W2, b2, out);
}

// round 15
// speedup vs baseline: 5.5457x; 1.0375x over previous
#include <cuda_runtime.h>
#include <cstdint>

#define DIM 256
#define FULL 0xffffffffu
typedef unsigned long long ull;
#define NEGM 0x8000000080000000ULL

__device__ __forceinline__ int par(int v) { return __popc(v) & 1; }

__device__ __forceinline__ ull pk(float a, float b) {
    ull d; asm("mov.b64 %0, {%1, %2};" : "=l"(d) : "f"(a), "f"(b)); return d;
}
__device__ __forceinline__ ull pk2(float s) { return pk(s, s); }
__device__ __forceinline__ float2 upk(ull v) {
    float a, b; asm("mov.b64 {%0, %1}, %2;" : "=f"(a), "=f"(b) : "l"(v));
    return make_float2(a, b);
}
__device__ __forceinline__ ull f2mul(ull a, ull b) {
    ull d; asm("mul.rn.f32x2 %0, %1, %2;" : "=l"(d) : "l"(a), "l"(b)); return d;
}
__device__ __forceinline__ ull f2add(ull a, ull b) {
    ull d; asm("add.rn.f32x2 %0, %1, %2;" : "=l"(d) : "l"(a), "l"(b)); return d;
}
__device__ __forceinline__ ull f2fma(ull a, ull b, ull c) {
    ull d; asm("fma.rn.f32x2 %0, %1, %2, %3;" : "=l"(d) : "l"(a), "l"(b), "l"(c)); return d;
}

__device__ __forceinline__ ull merge2p(ull a, ull b, int off, int lane4) {
    const bool sel = (lane4 & off) != 0;
    const ull xv = sel ? b : a;
    const ull yv = __shfl_xor_sync(FULL, sel ? a : b, off);
    return f2add(xv, yv);
}

// ---------------------------------------------------------------------------
// R14 circuit (verified) + reduced-cost expectation section:
//  - pair-restricted xp sums (half the terms, doubled once at the end)
//  - e/o decomposition of the signed power sums
// ---------------------------------------------------------------------------
__global__ void __launch_bounds__(256)
qml_bfly_kernel(const float* __restrict__ x, int Btot,
                const float* __restrict__ qw,
                const float* __restrict__ gg, const float* __restrict__ bb,
                const float* __restrict__ rm, const float* __restrict__ rv,
                const float* __restrict__ W1, const float* __restrict__ b1,
                const float* __restrict__ W2, const float* __restrict__ b2,
                float* __restrict__ out) {
    __shared__ float s_gc[16][4];
    __shared__ ull s_phc[DIM], s_phs[DIM];

    const int tid = threadIdx.x;
    const int lane = tid & 31;
    const int warp = tid >> 5;
    const int lane4 = lane & 15;
    const int half = lane >> 4;
    const int l4par = par(lane4);
    const int gb = lane & 16;

    if (tid < 16) {
        const float ty = qw[tid * 2 + 0];
        const float tz = qw[tid * 2 + 1];
        float sy, cy, sz, cz;
        sincosf(0.5f * ty, &sy, &cy);
        sincosf(0.5f * tz, &sz, &cz);
        s_gc[tid][0] = cy; s_gc[tid][1] = sy;
        s_gc[tid][2] = cz; s_gc[tid][3] = sz;
    }
    {
        float th = 0.0f;
#pragma unroll
        for (int w = 0; w < 8; ++w) {
            const float htz = 0.5f * qw[w * 2 + 1];
            th += ((tid >> (7 - w)) & 1) ? htz : -htz;
        }
        float sph, cph;
        sincosf(th, &sph, &cph);
        s_phc[tid] = pk2(cph);
        s_phs[tid] = pk2(sph);
    }
    __syncthreads();

    const int stride = gridDim.x * 32;
    for (int rb = blockIdx.x * 32 + warp * 4 + half * 2; rb < Btot; rb += stride) {
        const bool v0 = rb < Btot, v1 = rb + 1 < Btot;
        ull ar[16], ai[16];
        {
            const float4* xa = reinterpret_cast<const float4*>(
                x + (size_t)(v0 ? rb : 0) * DIM + lane4 * 16);
            const float4* xb = reinterpret_cast<const float4*>(
                x + (size_t)(v1 ? rb + 1 : 0) * DIM + lane4 * 16);
#pragma unroll
            for (int j = 0; j < 4; ++j) {
                const float4 A = v0 ? xa[j] : make_float4(0, 0, 0, 0);
                const float4 B = v1 ? xb[j] : make_float4(0, 0, 0, 0);
                ar[j * 4 + 0] = pk(A.x, B.x);
                ar[j * 4 + 1] = pk(A.y, B.y);
                ar[j * 4 + 2] = pk(A.z, B.z);
                ar[j * 4 + 3] = pk(A.w, B.w);
            }
        }

        // ========== LAYER 1 (real; RZ deferred) ==========
#pragma unroll
        for (int w = 0; w < 4; ++w) {
            const int Lm = 8 >> w;
            const ull cyP = pk2(s_gc[w][0]);
            ull ssyP = pk2(s_gc[w][1]);
            if (!(lane4 & Lm)) ssyP ^= NEGM;
#pragma unroll
            for (int r = 0; r < 16; ++r) {
                const ull pr = __shfl_xor_sync(FULL, ar[r], Lm);
                ar[r] = f2fma(ssyP, pr, f2mul(cyP, ar[r]));
            }
        }
#pragma unroll
        for (int w = 4; w < 8; ++w) {
            const int kb = 1 << (7 - w);
            const ull cyP = pk2(s_gc[w][0]);
            const ull syP = pk2(s_gc[w][1]);
            const ull nsyP = syP ^ NEGM;
#pragma unroll
            for (int r0 = 0; r0 < 16; ++r0) {
                if (!(r0 & kb)) {
                    const int r1 = r0 | kb;
                    const ull n0 = f2fma(nsyP, ar[r1], f2mul(cyP, ar[r0]));
                    const ull n1 = f2fma(syP, ar[r0], f2mul(cyP, ar[r1]));
                    ar[r0] = n0; ar[r1] = n1;
                }
            }
        }
#pragma unroll
        for (int r = 0; r < 16; ++r) {
            const ull c = s_phc[lane4 * 16 + r];
            const ull s = s_phs[lane4 * 16 + r];
            ai[r] = f2mul(ar[r], s);
            ar[r] = f2mul(ar[r], c);
        }

        // ========== LAYER 2 (complex; mu = P^-1) ==========
        {
            const int Lm_[3] = {12, 6, 3};
            const int Sm_[3] = {8, 12, 14};
#pragma unroll
            for (int w = 0; w < 3; ++w) {
                const int gid = 8 + w;
                const bool st = par(lane4 & Sm_[w]);
                const ull cyP = pk2(s_gc[gid][0]);
                const ull czP = pk2(s_gc[gid][2]);
                ull ssyP = pk2(s_gc[gid][1]);
                ull sszP = pk2(s_gc[gid][3]);
                if (!st) { ssyP ^= NEGM; sszP ^= NEGM; }
                const ull nsszP = sszP ^ NEGM;
#pragma unroll
                for (int r = 0; r < 16; ++r) {
                    const ull pr = __shfl_xor_sync(FULL, ar[r], Lm_[w]);
                    const ull pi = __shfl_xor_sync(FULL, ai[r], Lm_[w]);
                    const ull nr = f2fma(ssyP, pr, f2mul(cyP, ar[r]));
                    const ull ni = f2fma(ssyP, pi, f2mul(cyP, ai[r]));
                    ar[r] = f2fma(nsszP, ni, f2mul(czP, nr));
                    ai[r] = f2fma(sszP, nr, f2mul(czP, ni));
                }
            }
        }
        {
            const ull cyP = pk2(s_gc[11][0]);
            const ull czP = pk2(s_gc[11][2]);
            ull ssyP = pk2(s_gc[11][1]);
            ull sszP = pk2(s_gc[11][3]);
            if (!l4par) { ssyP ^= NEGM; sszP ^= NEGM; }
            const ull nsszP = sszP ^ NEGM;
#pragma unroll
            for (int r = 0; r < 8; ++r) {
                const ull p0r = __shfl_xor_sync(FULL, ar[r + 8], 1);
                const ull p0i = __shfl_xor_sync(FULL, ai[r + 8], 1);
                const ull p1r = __shfl_xor_sync(FULL, ar[r], 1);
                const ull p1i = __shfl_xor_sync(FULL, ai[r], 1);
                const ull nr0 = f2fma(ssyP, p0r, f2mul(cyP, ar[r]));
                const ull ni0 = f2fma(ssyP, p0i, f2mul(cyP, ai[r]));
                const ull nr1 = f2fma(ssyP, p1r, f2mul(cyP, ar[r + 8]));
                const ull ni1 = f2fma(ssyP, p1i, f2mul(cyP, ai[r + 8]));
                ar[r] = f2fma(nsszP, ni0, f2mul(czP, nr0));
                ai[r] = f2fma(sszP, nr0, f2mul(czP, ni0));
                ar[r + 8] = f2fma(nsszP, ni1, f2mul(czP, nr1));
                ai[r + 8] = f2fma(sszP, nr1, f2mul(czP, ni1));
            }
        }
        {
            const bool c = (l4par == 0);
            const int pairsA[4][8] = {
                {0, 1, 2, 3, 4, 5, 6, 7},
                {0, 1, 2, 3, 12, 13, 14, 15},
                {0, 1, 6, 7, 10, 11, 12, 13},
                {0, 3, 5, 6, 9, 10, 12, 15}
            };
            const int flips[4] = {12, 6, 3, 1};
#pragma unroll
            for (int w = 0; w < 4; ++w) {
                const int gid = 12 + w;
                const ull cyP = pk2(s_gc[gid][0]);
                const ull czP = pk2(s_gc[gid][2]);
                ull s1P = pk2(s_gc[gid][1]);
                ull s2P = pk2(s_gc[gid][3]);
                if (!c) { s1P ^= NEGM; s2P ^= NEGM; }
                const ull ns1P = s1P ^ NEGM;
                const ull ns2P = s2P ^ NEGM;
#pragma unroll
                for (int j = 0; j < 8; ++j) {
                    const int rA = pairsA[w][j];
                    const int rB = rA ^ flips[w];
                    const ull nAr = f2fma(ns1P, ar[rB], f2mul(cyP, ar[rA]));
                    const ull nAi = f2fma(ns1P, ai[rB], f2mul(cyP, ai[rA]));
                    const ull nBr = f2fma(s1P, ar[rA], f2mul(cyP, ar[rB]));
                    const ull nBi = f2fma(s1P, ai[rA], f2mul(cyP, ai[rB]));
                    ar[rA] = f2fma(s2P, nAi, f2mul(czP, nAr));
                    ai[rA] = f2fma(ns2P, nAr, f2mul(czP, nAi));
                    ar[rB] = f2fma(ns2P, nBi, f2mul(czP, nBr));
                    ai[rB] = f2fma(s2P, nBr, f2mul(czP, nBi));
                }
            }
        }

        // ========== expectations (mu = P^-2), reduced-cost ==========
        ull p[16];
#pragma unroll
        for (int r = 0; r < 16; ++r)
            p[r] = f2fma(ai[r], ai[r], f2mul(ar[r], ar[r]));
        // e/o decomposition over reg bit 3
        ull psum = 0ull, S8 = 0ull, S4m = 0ull, S10 = 0ull, S5m = 0ull;
#pragma unroll
        for (int r = 0; r < 8; ++r) {
            const ull e = f2add(p[r], p[r + 8]);
            const ull o = f2add(p[r], p[r + 8] ^ NEGM);
            psum = f2add(psum, e);
            S4m = f2add(S4m, par(r & 4) ? (e ^ NEGM) : e);
            S5m = f2add(S5m, par(r & 5) ? (e ^ NEGM) : e);
            S8  = f2add(S8, o);
            S10 = f2add(S10, par(r & 2) ? (o ^ NEGM) : o);
        }

        // xp partials (pair-restricted where possible; doubled below)
        ull x7p = 0ull, x6p = 0ull, x5p = 0ull, x4p = 0ull;
        ull x3p = 0ull, x2p = 0ull, x1p = 0ull, x0p = 0ull;
#pragma unroll
        for (int r = 0; r < 16; ++r) {
            if (!(r & 8))   // flip 10 (bits 3,1): bit3==0 side
                x3p = f2fma(ai[r], ai[r ^ 10], f2fma(ar[r], ar[r ^ 10], x3p));
            if (!(r & 4))   // flip 5 (bits 2,0): bit2==0 side
                x2p = f2fma(ai[r], ai[r ^ 5], f2fma(ar[r], ar[r ^ 5], x2p));
            if (!(r & 2))   // flip 2
                x1p = f2fma(ai[r], ai[r ^ 2], f2fma(ar[r], ar[r ^ 2], x1p));
            if (!(r & 1))   // flip 1
                x0p = f2fma(ai[r], ai[r ^ 1], f2fma(ar[r], ar[r ^ 1], x0p));
            // pure lane flips: all r
            x7p = f2fma(ar[r], __shfl_xor_sync(FULL, ar[r], 10), x7p);
            x7p = f2fma(ai[r], __shfl_xor_sync(FULL, ai[r], 10), x7p);
            x6p = f2fma(ar[r], __shfl_xor_sync(FULL, ar[r], 5), x6p);
            x6p = f2fma(ai[r], __shfl_xor_sync(FULL, ai[r], 5), x6p);
            if (!(r & 8)) { // flip reg8|lane2: reg-bit3==0 side
                x5p = f2fma(ar[r], __shfl_xor_sync(FULL, ar[r ^ 8], 2), x5p);
                x5p = f2fma(ai[r], __shfl_xor_sync(FULL, ai[r ^ 8], 2), x5p);
            }
            if (!(r & 4)) { // flip reg4|lane1: reg-bit2==0 side
                x4p = f2fma(ar[r], __shfl_xor_sync(FULL, ar[r ^ 4], 1), x4p);
                x4p = f2fma(ai[r], __shfl_xor_sync(FULL, ai[r ^ 4], 1), x4p);
            }
        }
        // double the half-pair sums
        x5p = f2add(x5p, x5p);
        x4p = f2add(x4p, x4p);
        x3p = f2add(x3p, x3p);
        x2p = f2add(x2p, x2p);
        x1p = f2add(x1p, x1p);
        x0p = f2add(x0p, x0p);

        // 4-stage lane-WHTs of psum, S8, S4m, S10, S5m
        ull w0 = psum, w1 = S8, w2 = S4m, w3 = S10, w4 = S5m;
#pragma unroll
        for (int off = 8; off; off >>= 1) {
            const ull nm = (lane4 & off) ? NEGM : 0ull;
            const ull t0 = __shfl_xor_sync(FULL, w0, off);
            const ull t1 = __shfl_xor_sync(FULL, w1, off);
            const ull t2 = __shfl_xor_sync(FULL, w2, off);
            const ull t3 = __shfl_xor_sync(FULL, w3, off);
            const ull t4 = __shfl_xor_sync(FULL, w4, off);
            w0 = f2add(t0, w0 ^ nm);
            w1 = f2add(t1, w1 ^ nm);
            w2 = f2add(t2, w2 ^ nm);
            w3 = f2add(t3, w3 ^ nm);
            w4 = f2add(t4, w4 ^ nm);
        }
        const ull normP = __shfl_sync(FULL, w0, gb | 0);
        const ull z7P = __shfl_sync(FULL, w0, gb | 8);
        const ull z6P = __shfl_sync(FULL, w0, gb | 4);
        const ull z5P = __shfl_sync(FULL, w0, gb | 10);
        const ull z4P = __shfl_sync(FULL, w0, gb | 5);
        const ull z3P = __shfl_sync(FULL, w1, gb | 10);
        const ull z2P = __shfl_sync(FULL, w2, gb | 5);
        const ull z1P = __shfl_sync(FULL, w3, gb | 10);
        const ull z0P = __shfl_sync(FULL, w4, gb | 5);

        const ull m0 = merge2p(x7p, x6p, 8, lane4);
        const ull m1 = merge2p(x5p, x4p, 8, lane4);
        const ull m2 = merge2p(x3p, x2p, 8, lane4);
        const ull m3 = merge2p(x1p, x0p, 8, lane4);
        const ull q0 = merge2p(m0, m1, 4, lane4);
        const ull q1 = merge2p(m2, m3, 4, lane4);
        ull r0 = merge2p(q0, q1, 2, lane4);
        r0 = f2add(r0, __shfl_xor_sync(FULL, r0, 1));
        const ull xv7P = __shfl_sync(FULL, r0, gb | 0);
        const ull xv6P = __shfl_sync(FULL, r0, gb | 8);
        const ull xv5P = __shfl_sync(FULL, r0, gb | 4);
        const ull xv4P = __shfl_sync(FULL, r0, gb | 12);
        const ull xv3P = __shfl_sync(FULL, r0, gb | 2);
        const ull xv2P = __shfl_sync(FULL, r0, gb | 10);
        const ull xv1P = __shfl_sync(FULL, r0, gb | 6);
        const ull xv0P = __shfl_sync(FULL, r0, gb | 14);

        const int wrow = rb + lane4;
        if (lane4 < 2 && wrow < Btot) {
            const bool hi = (lane4 == 1);
            const float2 nu = upk(normP);
            const float inv_n = 1.0f / (hi ? nu.y : nu.x);
            const ull zp[8]  = {z7P, z6P, z5P, z4P, z3P, z2P, z1P, z0P};
            const ull xpv[8] = {xv7P, xv6P, xv5P, xv4P, xv3P, xv2P, xv1P, xv0P};
            float q[16];
#pragma unroll
            for (int i = 0; i < 8; ++i) {
                const float2 a = upk(zp[i]);
                const float2 b = upk(xpv[i]);
                q[i]     = (hi ? a.y : a.x) * inv_n;
                q[8 + i] = (hi ? b.y : b.x) * inv_n;
            }
            float hbn[16];
#pragma unroll
            for (int i = 0; i < 16; ++i)
                hbn[i] = gg[i] * (q[i] - rm[i]) * rsqrtf(rv[i] + 1e-5f) + bb[i];
            float hh[8];
#pragma unroll
            for (int j = 0; j < 8; ++j) {
                float acc = b1[j];
#pragma unroll
                for (int i = 0; i < 16; ++i) acc += hbn[i] * W1[i * 8 + j];
                hh[j] = fmaxf(acc, 0.0f);
            }
#pragma unroll
            for (int k2 = 0; k2 < 2; ++k2) {
                float acc = b2[k2];
#pragma unroll
                for (int j = 0; j < 8; ++j) acc += hh[j] * W2[j * 2 + k2];
                out[(size_t)wrow * 2 + k2] = acc;
            }
        }
    }
}

// ---------------------------------------------------------------------------
extern "C" void kernel_launch(void* const* d_in, const int* in_sizes, int n_in,
                              void* d_out, int out_size) {
    const float* x  = (const float*)d_in[0];
    const float* qw = (const float*)d_in[1];
    const float* gg = (const float*)d_in[2];
    const float* bb = (const float*)d_in[3];
    const float* rm = (const float*)d_in[4];
    const float* rv = (const float*)d_in[5];
    const float* W1 = (const float*)d_in[6];
    const float* b1 = (const float*)d_in[7];
    const float* W2 = (const float*)d_in[8];
    const float* b2 = (const float*)d_in[9];
    float* out = (float*)d_out;

    const int Btot = in_sizes[0] / DIM;
    if (Btot <= 0) return;

    qml_bfly_kernel<<<2048, 256>>>(x, Btot, qw, gg, bb, rm, rv,
                                   W1, b1, W2, b2, out);
}

// round 17
// speedup vs baseline: 5.6426x; 1.0175x over previous
#include <cuda_runtime.h>
#include <cstdint>

#define DIM 256
#define FULL 0xffffffffu
typedef unsigned long long ull;
#define NEGM 0x8000000080000000ULL

__device__ __forceinline__ int par(int v) { return __popc(v) & 1; }

__device__ __forceinline__ ull pk(float a, float b) {
    ull d; asm("mov.b64 %0, {%1, %2};" : "=l"(d) : "f"(a), "f"(b)); return d;
}
__device__ __forceinline__ ull pk2(float s) { return pk(s, s); }
__device__ __forceinline__ float2 upk(ull v) {
    float a, b; asm("mov.b64 {%0, %1}, %2;" : "=f"(a), "=f"(b) : "l"(v));
    return make_float2(a, b);
}
__device__ __forceinline__ ull f2mul(ull a, ull b) {
    ull d; asm("mul.rn.f32x2 %0, %1, %2;" : "=l"(d) : "l"(a), "l"(b)); return d;
}
__device__ __forceinline__ ull f2add(ull a, ull b) {
    ull d; asm("add.rn.f32x2 %0, %1, %2;" : "=l"(d) : "l"(a), "l"(b)); return d;
}
__device__ __forceinline__ ull f2fma(ull a, ull b, ull c) {
    ull d; asm("fma.rn.f32x2 %0, %1, %2, %3;" : "=l"(d) : "l"(a), "l"(b), "l"(c)); return d;
}

__device__ __forceinline__ ull merge2p(ull a, ull b, int off, int lane) {
    const bool sel = (lane & off) != 0;
    const ull xv = sel ? b : a;
    const ull yv = __shfl_xor_sync(FULL, sel ? a : b, off);
    return f2add(xv, yv);
}

// ---------------------------------------------------------------------------
// R12 layout (lane = p>>3, reg r = p&7; masks verified at 155us), packed
// f32x2 over row pairs (one warp = 2 rows). State = 16 ull -> 3 CTAs/SM.
// Layer-2 under mu=P^-1, expectations under mu=P^-2.
// ---------------------------------------------------------------------------
__global__ void __launch_bounds__(256, 3)
qml_bfly_kernel(const float* __restrict__ x, int Btot,
                const float* __restrict__ qw,
                const float* __restrict__ gg, const float* __restrict__ bb,
                const float* __restrict__ rm, const float* __restrict__ rv,
                const float* __restrict__ W1, const float* __restrict__ b1,
                const float* __restrict__ W2, const float* __restrict__ b2,
                float* __restrict__ out) {
    __shared__ float s_gc[16][4];
    __shared__ ull s_phc[DIM], s_phs[DIM];

    const int tid = threadIdx.x;
    const int lane = tid & 31;
    const int warp = tid >> 5;
    const int lane_par = par(lane);

    if (tid < 16) {
        const float ty = qw[tid * 2 + 0];
        const float tz = qw[tid * 2 + 1];
        float sy, cy, sz, cz;
        sincosf(0.5f * ty, &sy, &cy);
        sincosf(0.5f * tz, &sz, &cz);
        s_gc[tid][0] = cy; s_gc[tid][1] = sy;
        s_gc[tid][2] = cz; s_gc[tid][3] = sz;
    }
    {
        float th = 0.0f;
#pragma unroll
        for (int w = 0; w < 8; ++w) {
            const float htz = 0.5f * qw[w * 2 + 1];
            th += ((tid >> (7 - w)) & 1) ? htz : -htz;
        }
        float sph, cph;
        sincosf(th, &sph, &cph);
        s_phc[tid] = pk2(cph);
        s_phs[tid] = pk2(sph);
    }
    __syncthreads();

    const int stride = gridDim.x * 16;
    for (int rb = (blockIdx.x * 8 + warp) * 2; rb < Btot; rb += stride) {
        const bool v0 = rb < Btot, v1 = rb + 1 < Btot;
        ull ar[8], ai[8];
        {
            const float4* xa = reinterpret_cast<const float4*>(
                x + (size_t)(v0 ? rb : 0) * DIM + lane * 8);
            const float4* xb = reinterpret_cast<const float4*>(
                x + (size_t)(v1 ? rb + 1 : 0) * DIM + lane * 8);
#pragma unroll
            for (int j = 0; j < 2; ++j) {
                const float4 A = v0 ? xa[j] : make_float4(0, 0, 0, 0);
                const float4 B = v1 ? xb[j] : make_float4(0, 0, 0, 0);
                ar[j * 4 + 0] = pk(A.x, B.x);
                ar[j * 4 + 1] = pk(A.y, B.y);
                ar[j * 4 + 2] = pk(A.z, B.z);
                ar[j * 4 + 3] = pk(A.w, B.w);
            }
        }

        // ========== LAYER 1 (real; RZ deferred) ==========
#pragma unroll
        for (int w = 0; w < 5; ++w) {
            const int Lm = 1 << (4 - w);
            const ull cyP = pk2(s_gc[w][0]);
            ull ssyP = pk2(s_gc[w][1]);
            if (!(lane & Lm)) ssyP ^= NEGM;
#pragma unroll
            for (int r = 0; r < 8; ++r) {
                const ull pr = __shfl_xor_sync(FULL, ar[r], Lm);
                ar[r] = f2fma(ssyP, pr, f2mul(cyP, ar[r]));
            }
        }
#pragma unroll
        for (int w = 5; w < 8; ++w) {
            const int kb = 1 << (7 - w);
            const ull cyP = pk2(s_gc[w][0]);
            const ull syP = pk2(s_gc[w][1]);
            const ull nsyP = syP ^ NEGM;
#pragma unroll
            for (int r0 = 0; r0 < 8; ++r0) {
                if (!(r0 & kb)) {
                    const int r1 = r0 | kb;
                    const ull n0 = f2fma(nsyP, ar[r1], f2mul(cyP, ar[r0]));
                    const ull n1 = f2fma(syP, ar[r0], f2mul(cyP, ar[r1]));
                    ar[r0] = n0; ar[r1] = n1;
                }
            }
        }
#pragma unroll
        for (int r = 0; r < 8; ++r) {
            const ull c = s_phc[lane * 8 + r];
            const ull s = s_phs[lane * 8 + r];
            ai[r] = f2mul(ar[r], s);
            ar[r] = f2mul(ar[r], c);
        }

        // ========== LAYER 2 (complex; mu = P^-1) ==========
        {
            const int Lm_[4] = {24, 12, 6, 3};
            const int Sm_[4] = {16, 24, 28, 30};
#pragma unroll
            for (int w = 0; w < 4; ++w) {
                const int gid = 8 + w;
                const bool st = par(lane & Sm_[w]);
                const ull cyP = pk2(s_gc[gid][0]);
                const ull czP = pk2(s_gc[gid][2]);
                ull ssyP = pk2(s_gc[gid][1]);
                ull sszP = pk2(s_gc[gid][3]);
                if (!st) { ssyP ^= NEGM; sszP ^= NEGM; }
                const ull nsszP = sszP ^ NEGM;
#pragma unroll
                for (int r = 0; r < 8; ++r) {
                    const ull pr = __shfl_xor_sync(FULL, ar[r], Lm_[w]);
                    const ull pi = __shfl_xor_sync(FULL, ai[r], Lm_[w]);
                    const ull nr = f2fma(ssyP, pr, f2mul(cyP, ar[r]));
                    const ull ni = f2fma(ssyP, pi, f2mul(cyP, ai[r]));
                    ar[r] = f2fma(nsszP, ni, f2mul(czP, nr));
                    ai[r] = f2fma(sszP, nr, f2mul(czP, ni));
                }
            }
        }
        // v=3 (gid 12): flip lane^1, reg^4; sign = par(lane)
        {
            const ull cyP = pk2(s_gc[12][0]);
            const ull czP = pk2(s_gc[12][2]);
            ull ssyP = pk2(s_gc[12][1]);
            ull sszP = pk2(s_gc[12][3]);
            if (!lane_par) { ssyP ^= NEGM; sszP ^= NEGM; }
            const ull nsszP = sszP ^ NEGM;
#pragma unroll
            for (int r = 0; r < 4; ++r) {
                const ull p0r = __shfl_xor_sync(FULL, ar[r + 4], 1);
                const ull p0i = __shfl_xor_sync(FULL, ai[r + 4], 1);
                const ull p1r = __shfl_xor_sync(FULL, ar[r], 1);
                const ull p1i = __shfl_xor_sync(FULL, ai[r], 1);
                const ull nr0 = f2fma(ssyP, p0r, f2mul(cyP, ar[r]));
                const ull ni0 = f2fma(ssyP, p0i, f2mul(cyP, ai[r]));
                const ull nr1 = f2fma(ssyP, p1r, f2mul(cyP, ar[r + 4]));
                const ull ni1 = f2fma(ssyP, p1i, f2mul(cyP, ai[r + 4]));
                ar[r] = f2fma(nsszP, ni0, f2mul(czP, nr0));
                ai[r] = f2fma(sszP, nr0, f2mul(czP, ni0));
                ar[r + 4] = f2fma(nsszP, ni1, f2mul(czP, nr1));
                ai[r + 4] = f2fma(sszP, nr1, f2mul(czP, ni1));
            }
        }
        // v=2..0 (gid 13..15): reg flips {6,3,1}; role c = (par(lane)==0)
        {
            const bool c = (lane_par == 0);
            const int pairsA[3][4] = {{0, 1, 2, 3}, {0, 1, 6, 7}, {0, 3, 5, 6}};
            const int flips[3] = {6, 3, 1};
#pragma unroll
            for (int w = 0; w < 3; ++w) {
                const int gid = 13 + w;
                const ull cyP = pk2(s_gc[gid][0]);
                const ull czP = pk2(s_gc[gid][2]);
                ull s1P = pk2(s_gc[gid][1]);
                ull s2P = pk2(s_gc[gid][3]);
                if (!c) { s1P ^= NEGM; s2P ^= NEGM; }
                const ull ns1P = s1P ^ NEGM;
                const ull ns2P = s2P ^ NEGM;
#pragma unroll
                for (int j = 0; j < 4; ++j) {
                    const int rA = pairsA[w][j];
                    const int rB = rA ^ flips[w];
                    const ull nAr = f2fma(ns1P, ar[rB], f2mul(cyP, ar[rA]));
                    const ull nAi = f2fma(ns1P, ai[rB], f2mul(cyP, ai[rA]));
                    const ull nBr = f2fma(s1P, ar[rA], f2mul(cyP, ar[rB]));
                    const ull nBi = f2fma(s1P, ai[rA], f2mul(cyP, ai[rB]));
                    ar[rA] = f2fma(s2P, nAi, f2mul(czP, nAr));
                    ai[rA] = f2fma(ns2P, nAr, f2mul(czP, nAi));
                    ar[rB] = f2fma(ns2P, nBi, f2mul(czP, nBr));
                    ai[rB] = f2fma(s2P, nBr, f2mul(czP, nBi));
                }
            }
        }

        // ========== expectations (mu = P^-2) ==========
        // e/o over reg bit 2: psum=+e, Sa=o, Sb=par(r&2) on e, Sc=par(r&1) on o
        ull psum = 0ull, Sa = 0ull, Sb = 0ull, Sc = 0ull;
#pragma unroll
        for (int r = 0; r < 4; ++r) {
            const ull pA = f2fma(ai[r], ai[r], f2mul(ar[r], ar[r]));
            const ull pB = f2fma(ai[r + 4], ai[r + 4], f2mul(ar[r + 4], ar[r + 4]));
            const ull e = f2add(pA, pB);
            const ull o = f2add(pA, pB ^ NEGM);
            psum = f2add(psum, e);
            Sb = f2add(Sb, par(r & 2) ? (e ^ NEGM) : e);
            Sa = f2add(Sa, o);
            Sc = f2add(Sc, par(r & 1) ? (o ^ NEGM) : o);
        }

        // xp partials (pair-restricted where possible; doubled below)
        ull xpp0 = 0ull, xpp1 = 0ull, xpp2 = 0ull, xpp3 = 0ull;
        ull xpp4 = 0ull, xpp5 = 0ull, xpp6 = 0ull, xpp7 = 0ull;
#pragma unroll
        for (int r = 0; r < 8; ++r) {
            if (!(r & 4))   // reg flip 5 (bits 2,0)
                xpp2 = f2fma(ai[r], ai[r ^ 5], f2fma(ar[r], ar[r ^ 5], xpp2));
            if (!(r & 2))   // reg flip 2
                xpp1 = f2fma(ai[r], ai[r ^ 2], f2fma(ar[r], ar[r ^ 2], xpp1));
            if (!(r & 1))   // reg flip 1
                xpp0 = f2fma(ai[r], ai[r ^ 1], f2fma(ar[r], ar[r ^ 1], xpp0));
            // pure lane flips (full)
            xpp7 = f2fma(ar[r], __shfl_xor_sync(FULL, ar[r], 20), xpp7);
            xpp7 = f2fma(ai[r], __shfl_xor_sync(FULL, ai[r], 20), xpp7);
            xpp6 = f2fma(ar[r], __shfl_xor_sync(FULL, ar[r], 10), xpp6);
            xpp6 = f2fma(ai[r], __shfl_xor_sync(FULL, ai[r], 10), xpp6);
            xpp5 = f2fma(ar[r], __shfl_xor_sync(FULL, ar[r], 5), xpp5);
            xpp5 = f2fma(ai[r], __shfl_xor_sync(FULL, ai[r], 5), xpp5);
            if (!(r & 4)) { // flip reg4 | lane2
                xpp4 = f2fma(ar[r], __shfl_xor_sync(FULL, ar[r ^ 4], 2), xpp4);
                xpp4 = f2fma(ai[r], __shfl_xor_sync(FULL, ai[r ^ 4], 2), xpp4);
            }
            if (!(r & 2)) { // flip reg2 | lane1
                xpp3 = f2fma(ar[r], __shfl_xor_sync(FULL, ar[r ^ 2], 1), xpp3);
                xpp3 = f2fma(ai[r], __shfl_xor_sync(FULL, ai[r ^ 2], 1), xpp3);
            }
        }
        xpp0 = f2add(xpp0, xpp0);
        xpp1 = f2add(xpp1, xpp1);
        xpp2 = f2add(xpp2, xpp2);
        xpp3 = f2add(xpp3, xpp3);
        xpp4 = f2add(xpp4, xpp4);

        // 5-stage lane-WHTs of psum, Sa, Sb, Sc
        ull w0 = psum, w1 = Sa, w2 = Sb, w3 = Sc;
#pragma unroll
        for (int off = 16; off; off >>= 1) {
            const ull nm = (lane & off) ? NEGM : 0ull;
            const ull t0 = __shfl_xor_sync(FULL, w0, off);
            const ull t1 = __shfl_xor_sync(FULL, w1, off);
            const ull t2 = __shfl_xor_sync(FULL, w2, off);
            const ull t3 = __shfl_xor_sync(FULL, w3, off);
            w0 = f2add(t0, w0 ^ nm);
            w1 = f2add(t1, w1 ^ nm);
            w2 = f2add(t2, w2 ^ nm);
            w3 = f2add(t3, w3 ^ nm);
        }
        const ull normP = __shfl_sync(FULL, w0, 0);
        const ull z7P = __shfl_sync(FULL, w0, 16);
        const ull z6P = __shfl_sync(FULL, w0, 8);
        const ull z5P = __shfl_sync(FULL, w0, 20);
        const ull z4P = __shfl_sync(FULL, w0, 10);
        const ull z3P = __shfl_sync(FULL, w0, 21);
        const ull z2P = __shfl_sync(FULL, w1, 10);
        const ull z1P = __shfl_sync(FULL, w2, 21);
        const ull z0P = __shfl_sync(FULL, w3, 10);

        // tree-merge the 8 xp sums (owner lanes 0,16,8,24,4,20,12,28)
        const ull m0 = merge2p(xpp0, xpp1, 16, lane);
        const ull m1 = merge2p(xpp2, xpp3, 16, lane);
        const ull m2 = merge2p(xpp4, xpp5, 16, lane);
        const ull m3 = merge2p(xpp6, xpp7, 16, lane);
        const ull q0 = merge2p(m0, m1, 8, lane);
        const ull q1 = merge2p(m2, m3, 8, lane);
        ull r0 = merge2p(q0, q1, 4, lane);
        r0 = f2add(r0, __shfl_xor_sync(FULL, r0, 2));
        r0 = f2add(r0, __shfl_xor_sync(FULL, r0, 1));
        const ull xv0P = __shfl_sync(FULL, r0, 0);
        const ull xv1P = __shfl_sync(FULL, r0, 16);
        const ull xv2P = __shfl_sync(FULL, r0, 8);
        const ull xv3P = __shfl_sync(FULL, r0, 24);
        const ull xv4P = __shfl_sync(FULL, r0, 4);
        const ull xv5P = __shfl_sync(FULL, r0, 20);
        const ull xv6P = __shfl_sync(FULL, r0, 12);
        const ull xv7P = __shfl_sync(FULL, r0, 28);

        const int wrow = rb + lane;
        if (lane < 2 && wrow < Btot) {
            const bool hi = (lane == 1);
            const float2 nu = upk(normP);
            const float inv_n = 1.0f / (hi ? nu.y : nu.x);
            const ull zp[8]  = {z7P, z6P, z5P, z4P, z3P, z2P, z1P, z0P};
            const ull xpv[8] = {xv7P, xv6P, xv5P, xv4P, xv3P, xv2P, xv1P, xv0P};
            float q[16];
#pragma unroll
            for (int i = 0; i < 8; ++i) {
                const float2 a = upk(zp[i]);
                const float2 b = upk(xpv[i]);
                q[i]     = (hi ? a.y : a.x) * inv_n;
                q[8 + i] = (hi ? b.y : b.x) * inv_n;
            }
            float hbn[16];
#pragma unroll
            for (int i = 0; i < 16; ++i)
                hbn[i] = gg[i] * (q[i] - rm[i]) * rsqrtf(rv[i] + 1e-5f) + bb[i];
            float hh[8];
#pragma unroll
            for (int j = 0; j < 8; ++j) {
                float acc = b1[j];
#pragma unroll
                for (int i = 0; i < 16; ++i) acc += hbn[i] * W1[i * 8 + j];
                hh[j] = fmaxf(acc, 0.0f);
            }
#pragma unroll
            for (int k2 = 0; k2 < 2; ++k2) {
                float acc = b2[k2];
#pragma unroll
                for (int j = 0; j < 8; ++j) acc += hh[j] * W2[j * 2 + k2];
                out[(size_t)wrow * 2 + k2] = acc;
            }
        }
    }
}

// ---------------------------------------------------------------------------
extern "C" void kernel_launch(void* const* d_in, const int* in_sizes, int n_in,
                              void* d_out, int out_size) {
    const float* x  = (const float*)d_in[0];
    const float* qw = (const float*)d_in[1];
    const float* gg = (const float*)d_in[2];
    const float* bb = (const float*)d_in[3];
    const float* rm = (const float*)d_in[4];
    const float* rv = (const float*)d_in[5];
    const float* W1 = (const float*)d_in[6];
    const float* b1 = (const float*)d_in[7];
    const float* W2 = (const float*)d_in[8];
    const float* b2 = (const float*)d_in[9];
    float* out = (float*)d_out;

    const int Btot = in_sizes[0] / DIM;
    if (Btot <= 0) return;

    qml_bfly_kernel<<<4096, 256>>>(x, Btot, qw, gg, bb, rm, rv,
                                   W1, b1, W2, b2, out);
}